// round 12
// baseline (speedup 1.0000x reference)
#include <cuda_runtime.h>
#include <cuda_bf16.h>
#include <cuda_fp16.h>
#include <math.h>
#include <stdint.h>

#define B_  2
#define S_  2048
#define E_  2048
#define H_  16
#define KV_ 4
#define D_  128
#define WIN_ 1024

// fp16 scratch
__device__ __half g_xhi[(size_t)B_ * S_ * E_];
__device__ __half g_wqhi[(size_t)H_ * D_ * E_];
__device__ __half g_wqlo[(size_t)H_ * D_ * E_];
__device__ __half g_wkhi[(size_t)KV_ * D_ * E_];
__device__ __half g_wklo[(size_t)KV_ * D_ * E_];
__device__ __half g_wvhi[(size_t)KV_ * D_ * E_];
__device__ __half g_wvlo[(size_t)KV_ * D_ * E_];
__device__ __half g_wohi[(size_t)E_ * H_ * D_];
__device__ __half g_wolo[(size_t)E_ * H_ * D_];
__device__ __half g_chi[(size_t)B_ * S_ * H_ * D_];

// fp16 attention operands
__device__ __half g_qh[(size_t)B_ * S_ * H_ * D_];
__device__ __half g_kh[(size_t)B_ * S_ * KV_ * D_];
__device__ __half g_kl[(size_t)B_ * S_ * KV_ * D_];
__device__ __half g_vh[(size_t)B_ * S_ * KV_ * D_];

// Q pre-scale: D^-0.5 * log2(e)  (softmax done in base-2)
#define QSCALE 0.12752820723310574f

// ---------------------------------------------------------------------------
// Fused fp16 splitter, 4 float2 per thread. x: hi only; weights: hi+lo.
// ---------------------------------------------------------------------------
#define N2_X  ((size_t)B_ * S_ * E_ / 2)
#define N2_WQ ((size_t)H_ * D_ * E_ / 2)
#define N2_WK ((size_t)KV_ * D_ * E_ / 2)
#define N2_ALL (N2_X + 2 * N2_WQ + 2 * N2_WK)

__global__ __launch_bounds__(256) void split_all(
    const float2* __restrict__ x,  const float2* __restrict__ wq,
    const float2* __restrict__ wk, const float2* __restrict__ wv,
    const float2* __restrict__ wo,
    __half2* __restrict__ xhi,
    __half2* __restrict__ qhi,  __half2* __restrict__ qlo,
    __half2* __restrict__ khi,  __half2* __restrict__ klo,
    __half2* __restrict__ vhi,  __half2* __restrict__ vlo,
    __half2* __restrict__ ohi,  __half2* __restrict__ olo)
{
    size_t g = ((size_t)blockIdx.x * blockDim.x + threadIdx.x) * 4;
    if (g >= N2_ALL) return;

    const float2* src;
    __half2 *dh, *dl;
    size_t off = g;
    if (off < N2_X)                    { src = x;  dh = xhi; dl = nullptr; }
    else if ((off -= N2_X) < N2_WQ)    { src = wq; dh = qhi; dl = qlo; }
    else if ((off -= N2_WQ) < N2_WK)   { src = wk; dh = khi; dl = klo; }
    else if ((off -= N2_WK) < N2_WK)   { src = wv; dh = vhi; dl = vlo; }
    else { off -= N2_WK;                 src = wo; dh = ohi; dl = olo; }

    float2 vv[4] = {src[off], src[off + 1], src[off + 2], src[off + 3]};
    #pragma unroll
    for (int u = 0; u < 4; u++) {
        __half h0 = __float2half(vv[u].x);
        __half h1 = __float2half(vv[u].y);
        __half2 hh; hh.x = h0; hh.y = h1;
        dh[off + u] = hh;
        if (dl) {
            __half2 ll;
            ll.x = __float2half(vv[u].x - __half2float(h0));
            ll.y = __float2half(vv[u].y - __half2float(h1));
            dl[off + u] = ll;
        }
    }
}

// ---------------------------------------------------------------------------
// PTX helpers
// ---------------------------------------------------------------------------
#define CP16(dst, src) \
    asm volatile("cp.async.cg.shared.global [%0], [%1], 16;\n" :: "r"(dst), "l"(src))
#define CP_COMMIT() asm volatile("cp.async.commit_group;\n" ::)
#define CP_WAIT2()  asm volatile("cp.async.wait_group 2;\n" ::)
#define CP_WAIT1()  asm volatile("cp.async.wait_group 1;\n" ::)
#define CP_WAIT0()  asm volatile("cp.async.wait_group 0;\n" ::)

#define LDSM4(R, addr) \
    asm volatile("ldmatrix.sync.aligned.m8n8.x4.shared.b16 {%0,%1,%2,%3}, [%4];\n" \
        : "=r"(R[0]), "=r"(R[1]), "=r"(R[2]), "=r"(R[3]) : "r"(addr))
#define LDSM4T(R, addr) \
    asm volatile("ldmatrix.sync.aligned.m8n8.x4.trans.shared.b16 {%0,%1,%2,%3}, [%4];\n" \
        : "=r"(R[0]), "=r"(R[1]), "=r"(R[2]), "=r"(R[3]) : "r"(addr))

#define MMAF16(acc, a, b0, b1) \
    asm volatile("mma.sync.aligned.m16n8k16.row.col.f32.f16.f16.f32 " \
        "{%0,%1,%2,%3}, {%4,%5,%6,%7}, {%8,%9}, {%0,%1,%2,%3};\n" \
        : "+f"(acc[0]), "+f"(acc[1]), "+f"(acc[2]), "+f"(acc[3]) \
        : "r"(a[0]), "r"(a[1]), "r"(a[2]), "r"(a[3]), "r"(b0), "r"(b1))

__device__ __forceinline__ float ex2f(float x) {
    float r;
    asm("ex2.approx.f32 %0, %1;" : "=f"(r) : "f"(x));
    return r;
}

// ---------------------------------------------------------------------------
// GEMM core (fp16 2-pass): C = Ah@Bh^T + Ah@Bl^T   (fp32 accum)
// 4-stage cp.async pipeline, 1 barrier/K16, 2 CTAs/SM.
// mode 0: fp32 out. mode 1: fp16 hi out. mode 2: rope+rms*oscale -> fp16.
// ---------------------------------------------------------------------------
#define SSTR   24
#define TILE_B (128u * SSTR * 2u)       // 6144 B
#define STG_B  (3u * TILE_B)            // Ah|Bh|Bl = 18432 B
#define G_SMEM (4u * STG_B)             // 73728 B

__device__ __forceinline__ void gemm_core(
    const __half* __restrict__ Ah,
    const __half* __restrict__ Bh, const __half* __restrict__ Bl,
    float* __restrict__ C,
    __half* __restrict__ Chh, __half* __restrict__ Chl,
    int N, int K, int bm, int bn, char* smem, int mode,
    const float* __restrict__ cs, const float* __restrict__ sn, float oscale)
{
    const uint32_t sb = (uint32_t)__cvta_generic_to_shared(smem);
    const int tid = threadIdx.x;
    const int lane = tid & 31;
    const int wid = tid >> 5;
    const int wm = wid & 1;
    const int wn = wid >> 1;

    const int lrow = tid >> 1;
    const int lkc  = tid & 1;
    const __half* gah = Ah + (size_t)(bm * 128 + lrow) * K + lkc * 8;
    const __half* gbh = Bh + (size_t)(bn * 128 + lrow) * K + lkc * 8;
    const __half* gbl = Bl + (size_t)(bn * 128 + lrow) * K + lkc * 8;
    const uint32_t sOff = (uint32_t)(lrow * SSTR + lkc * 8) * 2;

    const uint32_t aLn = (uint32_t)((wm * 64 + (lane & 15)) * SSTR + (lane >> 4) * 8) * 2;
    const uint32_t bLn = (uint32_t)((wn * 32 + ((lane >> 4) << 3) + (lane & 7)) * SSTR
                                    + ((lane >> 3) & 1) * 8) * 2;

    float acc[4][4][4];
    #pragma unroll
    for (int i = 0; i < 4; i++)
        #pragma unroll
        for (int j = 0; j < 4; j++)
            #pragma unroll
            for (int r = 0; r < 4; r++) acc[i][j][r] = 0.f;

    const int T = K / 16;

    auto stage_load = [&](uint32_t st, int kt) {
        uint32_t base = sb + st * STG_B + sOff;
        CP16(base,              gah + kt * 16);
        CP16(base + TILE_B,     gbh + kt * 16);
        CP16(base + 2 * TILE_B, gbl + kt * 16);
        CP_COMMIT();
    };

    stage_load(0, 0);
    stage_load(1, 1);
    stage_load(2, 2);

    for (int t = 0; t < T; t++) {
        CP_WAIT2();
        __syncthreads();

        const uint32_t ab = sb + (uint32_t)(t & 3) * STG_B;
        const uint32_t bb = ab + TILE_B;

        uint32_t ah[4][4], bh[2][4], bl[2][4];
        #pragma unroll
        for (int mt = 0; mt < 4; mt++)
            LDSM4(ah[mt], ab + aLn + mt * (16 * SSTR * 2));
        #pragma unroll
        for (int pr = 0; pr < 2; pr++) {
            LDSM4(bh[pr], bb + bLn + pr * (16 * SSTR * 2));
            LDSM4(bl[pr], bb + TILE_B + bLn + pr * (16 * SSTR * 2));
        }

        if (t + 3 < T) stage_load((uint32_t)((t + 3) & 3), t + 3);
        else           CP_COMMIT();

        #pragma unroll
        for (int mt = 0; mt < 4; mt++)
            #pragma unroll
            for (int nt = 0; nt < 4; nt++) {
                const int pr = nt >> 1, q = (nt & 1) * 2;
                MMAF16(acc[mt][nt], ah[mt], bh[pr][q], bh[pr][q + 1]);
            }
        #pragma unroll
        for (int mt = 0; mt < 4; mt++)
            #pragma unroll
            for (int nt = 0; nt < 4; nt++) {
                const int pr = nt >> 1, q = (nt & 1) * 2;
                MMAF16(acc[mt][nt], ah[mt], bl[pr][q], bl[pr][q + 1]);
            }
    }

    if (mode == 0) {
        #pragma unroll
        for (int mt = 0; mt < 4; mt++) {
            const int r0 = bm * 128 + wm * 64 + mt * 16 + (lane >> 2);
            #pragma unroll
            for (int nt = 0; nt < 4; nt++) {
                const int c0 = bn * 128 + wn * 32 + nt * 8 + (lane & 3) * 2;
                *(float2*)&C[(size_t)r0 * N + c0] =
                    make_float2(acc[mt][nt][0], acc[mt][nt][1]);
                *(float2*)&C[(size_t)(r0 + 8) * N + c0] =
                    make_float2(acc[mt][nt][2], acc[mt][nt][3]);
            }
        }
    } else if (mode == 1) {
        #pragma unroll
        for (int mt = 0; mt < 4; mt++) {
            const int r0 = bm * 128 + wm * 64 + mt * 16 + (lane >> 2);
            #pragma unroll
            for (int nt = 0; nt < 4; nt++) {
                const int c0 = bn * 128 + wn * 32 + nt * 8 + (lane & 3) * 2;
                #pragma unroll
                for (int hf = 0; hf < 2; hf++) {
                    __half2 hh = __floats2half2_rn(acc[mt][nt][hf * 2],
                                                   acc[mt][nt][hf * 2 + 1]);
                    *(uint32_t*)&Chh[(size_t)(r0 + hf * 8) * N + c0] =
                        *(uint32_t*)&hh;
                }
            }
        }
    } else {
        // mode 2: rope + rmsnorm (+oscale) fused epilogue -> fp16 hi (+lo)
        CP_WAIT0();
        __syncthreads();
        float* st = (float*)smem;
        #pragma unroll
        for (int mt = 0; mt < 4; mt++) {
            const int r0 = wm * 64 + mt * 16 + (lane >> 2);
            #pragma unroll
            for (int nt = 0; nt < 4; nt++) {
                const int c0 = wn * 32 + nt * 8 + (lane & 3) * 2;
                *(float2*)&st[r0 * 132 + c0] =
                    make_float2(acc[mt][nt][0], acc[mt][nt][1]);
                *(float2*)&st[(r0 + 8) * 132 + c0] =
                    make_float2(acc[mt][nt][2], acc[mt][nt][3]);
            }
        }
        __syncthreads();

        const int cb = bn * 128;
        for (int rr = 0; rr < 16; rr++) {
            int r = wid * 16 + rr;
            int grow_ = bm * 128 + r;
            int s = grow_ & (S_ - 1);
            float x1a = st[r * 132 + lane],      float_x1b = 0.f;
            float x1b = st[r * 132 + lane + 32];
            (void)float_x1b;
            float x2a = st[r * 132 + lane + 64], x2b = st[r * 132 + lane + 96];
            float ca = cs[s * 64 + lane], cbv = cs[s * 64 + lane + 32];
            float sa = sn[s * 64 + lane], sbv = sn[s * 64 + lane + 32];

            float o1a =  x1a * ca  + x2a * sa;
            float o1b =  x1b * cbv + x2b * sbv;
            float o2a = -x1a * sa  + x2a * ca;
            float o2b = -x1b * sbv + x2b * cbv;

            float ss = o1a * o1a + o1b * o1b + o2a * o2a + o2b * o2b;
            #pragma unroll
            for (int o = 16; o; o >>= 1) ss += __shfl_xor_sync(0xffffffffu, ss, o);
            float scale = rsqrtf(ss * (1.f / 128.f) + 1.1920928955078125e-07f)
                        * oscale;

            float v4[4] = {o1a * scale, o1b * scale, o2a * scale, o2b * scale};
            size_t gb = (size_t)grow_ * N + cb + lane;
            #pragma unroll
            for (int u = 0; u < 4; u++) {
                __half hh = __float2half(v4[u]);
                Chh[gb + u * 32] = hh;
                if (Chl) Chl[gb + u * 32] =
                    __float2half(v4[u] - __half2float(hh));
            }
        }
    }
}

// Fused Q/K/V projection + rope/rms epilogue (Q: hi scaled, K: hi+lo); V: hi.
__global__ __launch_bounds__(256, 2) void gemm_qkv(
    const __half* __restrict__ xh,
    const __half* __restrict__ wqh, const __half* __restrict__ wql,
    const __half* __restrict__ wkh, const __half* __restrict__ wkl,
    const __half* __restrict__ wvh, const __half* __restrict__ wvl,
    __half* __restrict__ qh, __half* __restrict__ kh, __half* __restrict__ kl,
    __half* __restrict__ vh,
    const float* __restrict__ cosp, const float* __restrict__ sinp)
{
    extern __shared__ char smem[];
    const int bx = blockIdx.x;
    if (bx < 16) {
        gemm_core(xh, wqh, wql, nullptr, qh, nullptr,
                  H_ * D_, E_, blockIdx.y, bx, smem, 2, cosp, sinp, QSCALE);
    } else if (bx < 20) {
        gemm_core(xh, wkh, wkl, nullptr, kh, kl,
                  KV_ * D_, E_, blockIdx.y, bx - 16, smem, 2, cosp, sinp, 1.f);
    } else {
        gemm_core(xh, wvh, wvl, nullptr, vh, nullptr,
                  KV_ * D_, E_, blockIdx.y, bx - 20, smem, 1, nullptr, nullptr, 1.f);
    }
}

__global__ __launch_bounds__(256, 2) void gemm_one(
    const __half* __restrict__ Ah,
    const __half* __restrict__ Bh, const __half* __restrict__ Bl,
    float* __restrict__ C, int N, int K)
{
    extern __shared__ char smem[];
    gemm_core(Ah, Bh, Bl, C, nullptr, nullptr, N, K,
              blockIdx.y, blockIdx.x, smem, 0, nullptr, nullptr, 1.f);
}

// ---------------------------------------------------------------------------
// fp16 2-pass sliding-window flash attention; softmax in base-2.
// 2 CTAs/SM (regs capped at 128; per-kt P conversion keeps live set small).
// ---------------------------------------------------------------------------
#define RB 17408   // 64 rows * 272 B (stride 136 fp16)
#define A_SMEM (6u * RB)   // 104448; x2 CTAs = 208896 <= 228KB

__global__ __launch_bounds__(256, 2) void attn_mma(
    const __half* __restrict__ q_, const __half* __restrict__ kh_,
    const __half* __restrict__ kl_, const __half* __restrict__ vh_,
    __half* __restrict__ chi)
{
    extern __shared__ char smem[];
    const uint32_t sbase = (uint32_t)__cvta_generic_to_shared(smem);

    const int tid = threadIdx.x, lane = tid & 31, w = tid >> 5;
    const int q0 = blockIdx.x * 128;
    const int h  = blockIdx.y, b = blockIdx.z;
    const int kvh = h >> 2;

    {
        int r = tid >> 1;
        size_t gbase = ((size_t)(b * S_ + q0 + r)) * (H_ * D_) + h * D_;
        const uint4* gq = (const uint4*)(q_ + gbase);
        #pragma unroll
        for (int u = 0; u < 8; u++) {
            int c = (tid & 1) * 8 + u;
            *(uint4*)(smem + (size_t)r * 272 + c * 16) = gq[c];
        }
    }
    __syncthreads();

    uint32_t ah[8][4];
    {
        uint32_t qro = (uint32_t)((w * 16 + (lane & 15)) * 272);
        #pragma unroll
        for (int d = 0; d < 8; d++) {
            uint32_t co = (uint32_t)((d * 16 + (lane >> 4) * 8) * 2);
            LDSM4(ah[d], sbase + qro + co);
        }
    }
    __syncthreads();

    float pacc[16][4];
    #pragma unroll
    for (int g = 0; g < 16; g++)
        #pragma unroll
        for (int r = 0; r < 4; r++) pacc[g][r] = 0.f;

    float m_run0 = -1e30f, m_run1 = -1e30f, l0 = 0.f, l1 = 0.f;

    const int ibase = q0 + w * 16;
    const int i0 = ibase + (lane >> 2);
    const int i1 = i0 + 8;

    int t0 = q0 - 1024; if (t0 < 0) t0 = 0;
    const int n = (q0 + 128 - t0) >> 6;

    const int crow = tid >> 2;
    const size_t grow = ((size_t)b * S_) * (KV_ * D_) + (size_t)kvh * D_;

    {
        size_t gb = grow + (size_t)(t0 + crow) * (KV_ * D_);
        #pragma unroll
        for (int u = 0; u < 4; u++) {
            int c = (tid & 3) * 4 + u;
            uint32_t so = (uint32_t)(crow * 272 + c * 16);
            CP16(sbase + so,          kh_ + gb + c * 8);
            CP16(sbase + RB + so,     kl_ + gb + c * 8);
            CP16(sbase + 2 * RB + so, vh_ + gb + c * 8);
        }
        CP_COMMIT();
    }

    for (int it = 0; it < n; it++) {
        const int t = t0 + it * 64;
        if (it + 1 < n) {
            uint32_t st = (uint32_t)((it + 1) & 1) * 3 * RB;
            size_t gb = grow + (size_t)(t + 64 + crow) * (KV_ * D_);
            #pragma unroll
            for (int u = 0; u < 4; u++) {
                int c = (tid & 3) * 4 + u;
                uint32_t so = st + (uint32_t)(crow * 272 + c * 16);
                CP16(sbase + so,          kh_ + gb + c * 8);
                CP16(sbase + RB + so,     kl_ + gb + c * 8);
                CP16(sbase + 2 * RB + so, vh_ + gb + c * 8);
            }
            CP_COMMIT();
            CP_WAIT1();
        } else {
            CP_WAIT0();
        }
        __syncthreads();

        const uint32_t khb = sbase + (uint32_t)(it & 1) * 3 * RB;
        const uint32_t klb = khb + RB;
        const uint32_t vhb = khb + 2 * RB;

        float sacc[8][4];
        #pragma unroll
        for (int g = 0; g < 8; g++)
            #pragma unroll
            for (int r = 0; r < 4; r++) sacc[g][r] = 0.f;

        #pragma unroll
        for (int d = 0; d < 8; d++) {
            uint32_t co = (uint32_t)((d * 16 + ((lane >> 3) & 1) * 8) * 2);
            #pragma unroll
            for (int g = 0; g < 4; g++) {
                uint32_t ro = (uint32_t)((g * 16 + ((lane >> 4) << 3) + (lane & 7)) * 272);
                uint32_t k4h[4], k4l[4];
                LDSM4(k4h, khb + ro + co);
                LDSM4(k4l, klb + ro + co);
                MMAF16(sacc[2 * g],     ah[d], k4h[0], k4h[1]);
                MMAF16(sacc[2 * g],     ah[d], k4l[0], k4l[1]);
                MMAF16(sacc[2 * g + 1], ah[d], k4h[2], k4h[3]);
                MMAF16(sacc[2 * g + 1], ah[d], k4l[2], k4l[3]);
            }
        }

        const bool need_mask = (t + 63 >= ibase) || (t + 1009 <= ibase);
        float m0 = -INFINITY, m1 = -INFINITY;
        #pragma unroll
        for (int g = 0; g < 8; g++) {
            float s0 = sacc[g][0], s1 = sacc[g][1];
            float s2 = sacc[g][2], s3 = sacc[g][3];
            if (need_mask) {
                int jb = t + g * 8 + 2 * (lane & 3);
                s0 = ((jb     <= i0) && (i0 - jb < 1024))     ? s0 : -INFINITY;
                s1 = ((jb + 1 <= i0) && (i0 - jb - 1 < 1024)) ? s1 : -INFINITY;
                s2 = ((jb     <= i1) && (i1 - jb < 1024))     ? s2 : -INFINITY;
                s3 = ((jb + 1 <= i1) && (i1 - jb - 1 < 1024)) ? s3 : -INFINITY;
                sacc[g][0] = s0; sacc[g][1] = s1;
                sacc[g][2] = s2; sacc[g][3] = s3;
            }
            m0 = fmaxf(m0, fmaxf(s0, s1));
            m1 = fmaxf(m1, fmaxf(s2, s3));
        }
        m0 = fmaxf(m0, __shfl_xor_sync(0xffffffffu, m0, 1));
        m0 = fmaxf(m0, __shfl_xor_sync(0xffffffffu, m0, 2));
        m1 = fmaxf(m1, __shfl_xor_sync(0xffffffffu, m1, 1));
        m1 = fmaxf(m1, __shfl_xor_sync(0xffffffffu, m1, 2));

        float mn0 = fmaxf(m_run0, m0), mn1 = fmaxf(m_run1, m1);
        float a0 = ex2f(m_run0 - mn0), a1 = ex2f(m_run1 - mn1);
        m_run0 = mn0; m_run1 = mn1;

        float rs0 = 0.f, rs1 = 0.f;
        #pragma unroll
        for (int g = 0; g < 8; g++) {
            float p0 = ex2f(sacc[g][0] - mn0);
            float p1 = ex2f(sacc[g][1] - mn0);
            float p2 = ex2f(sacc[g][2] - mn1);
            float p3 = ex2f(sacc[g][3] - mn1);
            sacc[g][0] = p0; sacc[g][1] = p1; sacc[g][2] = p2; sacc[g][3] = p3;
            rs0 += p0 + p1; rs1 += p2 + p3;
        }
        rs0 += __shfl_xor_sync(0xffffffffu, rs0, 1);
        rs0 += __shfl_xor_sync(0xffffffffu, rs0, 2);
        rs1 += __shfl_xor_sync(0xffffffffu, rs1, 1);
        rs1 += __shfl_xor_sync(0xffffffffu, rs1, 2);
        l0 = l0 * a0 + rs0;
        l1 = l1 * a1 + rs1;

        #pragma unroll
        for (int g = 0; g < 16; g++) {
            pacc[g][0] *= a0; pacc[g][1] *= a0;
            pacc[g][2] *= a1; pacc[g][3] *= a1;
        }

        // per-kt P conversion + PV (small live set)
        #pragma unroll
        for (int kt = 0; kt < 4; kt++) {
            uint32_t ph[4], pl[4];
            #pragma unroll
            for (int qq = 0; qq < 2; qq++) {
                #pragma unroll
                for (int r2 = 0; r2 < 2; r2++) {
                    float x0 = sacc[2 * kt + qq][r2 * 2];
                    float x1 = sacc[2 * kt + qq][r2 * 2 + 1];
                    __half2 hh = __floats2half2_rn(x0, x1);
                    __half2 ll = __floats2half2_rn(
                        x0 - __half2float(hh.x), x1 - __half2float(hh.y));
                    ph[qq * 2 + r2] = *(uint32_t*)&hh;
                    pl[qq * 2 + r2] = *(uint32_t*)&ll;
                }
            }
            uint32_t ro = (uint32_t)((kt * 16 + (lane & 15)) * 272);
            uint32_t co = (uint32_t)(((lane >> 4) * 8) * 2);
            #pragma unroll
            for (int g = 0; g < 8; g++) {
                uint32_t v4h[4];
                LDSM4T(v4h, vhb + ro + co + g * 32);
                MMAF16(pacc[2 * g],     ph, v4h[0], v4h[1]);
                MMAF16(pacc[2 * g],     pl, v4h[0], v4h[1]);
                MMAF16(pacc[2 * g + 1], ph, v4h[2], v4h[3]);
                MMAF16(pacc[2 * g + 1], pl, v4h[2], v4h[3]);
            }
        }
        __syncthreads();
    }

    float inv0 = 1.f / l0, inv1 = 1.f / l1;
    size_t base0 = ((size_t)(b * S_ + i0)) * (H_ * D_) + h * D_;
    size_t base1 = base0 + (size_t)8 * (H_ * D_);
    #pragma unroll
    for (int g = 0; g < 16; g++) {
        int col = g * 8 + 2 * (lane & 3);
        __half2 h0 = __floats2half2_rn(pacc[g][0] * inv0, pacc[g][1] * inv0);
        __half2 h1 = __floats2half2_rn(pacc[g][2] * inv1, pacc[g][3] * inv1);
        *(uint32_t*)&chi[base0 + col] = *(uint32_t*)&h0;
        *(uint32_t*)&chi[base1 + col] = *(uint32_t*)&h1;
    }
}

// ---------------------------------------------------------------------------
extern "C" void kernel_launch(void* const* d_in, const int* in_sizes, int n_in,
                              void* d_out, int out_size)
{
    const float* x    = (const float*)d_in[0];
    const float* cosp = (const float*)d_in[1];
    const float* sinp = (const float*)d_in[2];
    const float* Wq   = (const float*)d_in[3];
    const float* Wk   = (const float*)d_in[4];
    const float* Wv   = (const float*)d_in[5];
    const float* Wo   = (const float*)d_in[6];
    float* out = (float*)d_out;

    __half *xhi, *wqhi, *wqlo, *wkhi, *wklo, *wvhi, *wvlo, *wohi, *wolo;
    __half *chi, *qh, *kh, *kl, *vh;
    cudaGetSymbolAddress((void**)&xhi, g_xhi);
    cudaGetSymbolAddress((void**)&wqhi, g_wqhi);
    cudaGetSymbolAddress((void**)&wqlo, g_wqlo);
    cudaGetSymbolAddress((void**)&wkhi, g_wkhi);
    cudaGetSymbolAddress((void**)&wklo, g_wklo);
    cudaGetSymbolAddress((void**)&wvhi, g_wvhi);
    cudaGetSymbolAddress((void**)&wvlo, g_wvlo);
    cudaGetSymbolAddress((void**)&wohi, g_wohi);
    cudaGetSymbolAddress((void**)&wolo, g_wolo);
    cudaGetSymbolAddress((void**)&chi, g_chi);
    cudaGetSymbolAddress((void**)&qh, g_qh);
    cudaGetSymbolAddress((void**)&kh, g_kh);
    cudaGetSymbolAddress((void**)&kl, g_kl);
    cudaGetSymbolAddress((void**)&vh, g_vh);

    static bool attr_done = false;
    if (!attr_done) {
        cudaFuncSetAttribute(attn_mma,
            cudaFuncAttributeMaxDynamicSharedMemorySize, A_SMEM);
        cudaFuncSetAttribute(gemm_qkv,
            cudaFuncAttributeMaxDynamicSharedMemorySize, G_SMEM);
        cudaFuncSetAttribute(gemm_one,
            cudaFuncAttributeMaxDynamicSharedMemorySize, G_SMEM);
        attr_done = true;
    }

    const int M = B_ * S_;

    // fused split (4 float2 per thread; x hi-only)
    {
        size_t blocks = (N2_ALL / 4 + 255) / 256;
        split_all<<<(unsigned)blocks, 256>>>(
            (const float2*)x, (const float2*)Wq, (const float2*)Wk,
            (const float2*)Wv, (const float2*)Wo,
            (__half2*)xhi,
            (__half2*)wqhi, (__half2*)wqlo,
            (__half2*)wkhi, (__half2*)wklo,
            (__half2*)wvhi, (__half2*)wvlo,
            (__half2*)wohi, (__half2*)wolo);
    }

    // fused Q/K/V projections + rope/rms epilogue
    gemm_qkv<<<dim3(24, M / 128), 256, G_SMEM>>>(
        xhi, wqhi, wqlo, wkhi, wklo, wvhi, wvlo,
        qh, kh, kl, vh, cosp, sinp);

    // attention (2 CTAs/SM)
    attn_mma<<<dim3(S_ / 128, H_, B_), 256, A_SMEM>>>(
        qh, kh, kl, vh, chi);

    // output projection
    gemm_one<<<dim3(E_ / 128, M / 128), 256, G_SMEM>>>(
        chi, wohi, wolo, out, E_, E_);
}

// round 13
// speedup vs baseline: 1.0766x; 1.0766x over previous
#include <cuda_runtime.h>
#include <cuda_bf16.h>
#include <cuda_fp16.h>
#include <math.h>
#include <stdint.h>

#define B_  2
#define S_  2048
#define E_  2048
#define H_  16
#define KV_ 4
#define D_  128
#define WIN_ 1024

// fp16 scratch
__device__ __half g_xhi[(size_t)B_ * S_ * E_];
__device__ __half g_wqhi[(size_t)H_ * D_ * E_];
__device__ __half g_wqlo[(size_t)H_ * D_ * E_];
__device__ __half g_wkhi[(size_t)KV_ * D_ * E_];
__device__ __half g_wklo[(size_t)KV_ * D_ * E_];
__device__ __half g_wvhi[(size_t)KV_ * D_ * E_];
__device__ __half g_wvlo[(size_t)KV_ * D_ * E_];
__device__ __half g_wohi[(size_t)E_ * H_ * D_];
__device__ __half g_wolo[(size_t)E_ * H_ * D_];
__device__ __half g_chi[(size_t)B_ * S_ * H_ * D_];

// fp16 attention operands
__device__ __half g_qh[(size_t)B_ * S_ * H_ * D_];
__device__ __half g_kh[(size_t)B_ * S_ * KV_ * D_];
__device__ __half g_kl[(size_t)B_ * S_ * KV_ * D_];
__device__ __half g_vh[(size_t)B_ * S_ * KV_ * D_];

// Q pre-scale: D^-0.5 * log2(e)  (softmax done in base-2)
#define QSCALE 0.12752820723310574f

// ---------------------------------------------------------------------------
// Fused fp16 splitter, 4 float2 per thread. x: hi only; weights: hi+lo.
// ---------------------------------------------------------------------------
#define N2_X  ((size_t)B_ * S_ * E_ / 2)
#define N2_WQ ((size_t)H_ * D_ * E_ / 2)
#define N2_WK ((size_t)KV_ * D_ * E_ / 2)
#define N2_ALL (N2_X + 2 * N2_WQ + 2 * N2_WK)

__global__ __launch_bounds__(256) void split_all(
    const float2* __restrict__ x,  const float2* __restrict__ wq,
    const float2* __restrict__ wk, const float2* __restrict__ wv,
    const float2* __restrict__ wo,
    __half2* __restrict__ xhi,
    __half2* __restrict__ qhi,  __half2* __restrict__ qlo,
    __half2* __restrict__ khi,  __half2* __restrict__ klo,
    __half2* __restrict__ vhi,  __half2* __restrict__ vlo,
    __half2* __restrict__ ohi,  __half2* __restrict__ olo)
{
    size_t g = ((size_t)blockIdx.x * blockDim.x + threadIdx.x) * 4;
    if (g >= N2_ALL) return;

    const float2* src;
    __half2 *dh, *dl;
    size_t off = g;
    if (off < N2_X)                    { src = x;  dh = xhi; dl = nullptr; }
    else if ((off -= N2_X) < N2_WQ)    { src = wq; dh = qhi; dl = qlo; }
    else if ((off -= N2_WQ) < N2_WK)   { src = wk; dh = khi; dl = klo; }
    else if ((off -= N2_WK) < N2_WK)   { src = wv; dh = vhi; dl = vlo; }
    else { off -= N2_WK;                 src = wo; dh = ohi; dl = olo; }

    float2 vv[4] = {src[off], src[off + 1], src[off + 2], src[off + 3]};
    #pragma unroll
    for (int u = 0; u < 4; u++) {
        __half h0 = __float2half(vv[u].x);
        __half h1 = __float2half(vv[u].y);
        __half2 hh; hh.x = h0; hh.y = h1;
        dh[off + u] = hh;
        if (dl) {
            __half2 ll;
            ll.x = __float2half(vv[u].x - __half2float(h0));
            ll.y = __float2half(vv[u].y - __half2float(h1));
            dl[off + u] = ll;
        }
    }
}

// ---------------------------------------------------------------------------
// PTX helpers
// ---------------------------------------------------------------------------
#define CP16(dst, src) \
    asm volatile("cp.async.cg.shared.global [%0], [%1], 16;\n" :: "r"(dst), "l"(src))
#define CP_COMMIT() asm volatile("cp.async.commit_group;\n" ::)
#define CP_WAIT2()  asm volatile("cp.async.wait_group 2;\n" ::)
#define CP_WAIT1()  asm volatile("cp.async.wait_group 1;\n" ::)
#define CP_WAIT0()  asm volatile("cp.async.wait_group 0;\n" ::)

#define LDSM4(R, addr) \
    asm volatile("ldmatrix.sync.aligned.m8n8.x4.shared.b16 {%0,%1,%2,%3}, [%4];\n" \
        : "=r"(R[0]), "=r"(R[1]), "=r"(R[2]), "=r"(R[3]) : "r"(addr))
#define LDSM4T(R, addr) \
    asm volatile("ldmatrix.sync.aligned.m8n8.x4.trans.shared.b16 {%0,%1,%2,%3}, [%4];\n" \
        : "=r"(R[0]), "=r"(R[1]), "=r"(R[2]), "=r"(R[3]) : "r"(addr))

#define MMAF16(acc, a, b0, b1) \
    asm volatile("mma.sync.aligned.m16n8k16.row.col.f32.f16.f16.f32 " \
        "{%0,%1,%2,%3}, {%4,%5,%6,%7}, {%8,%9}, {%0,%1,%2,%3};\n" \
        : "+f"(acc[0]), "+f"(acc[1]), "+f"(acc[2]), "+f"(acc[3]) \
        : "r"(a[0]), "r"(a[1]), "r"(a[2]), "r"(a[3]), "r"(b0), "r"(b1))

__device__ __forceinline__ float ex2f(float x) {
    float r;
    asm("ex2.approx.f32 %0, %1;" : "=f"(r) : "f"(x));
    return r;
}

// ---------------------------------------------------------------------------
// GEMM core (fp16 2-pass): C = Ah@Bh^T + Ah@Bl^T   (fp32 accum)
// 4-stage cp.async pipeline, 1 barrier/K16, 2 CTAs/SM.
// mode 0: fp32 out. mode 1: fp16 hi out. mode 2: rope+rms*oscale -> fp16.
// ---------------------------------------------------------------------------
#define SSTR   24
#define TILE_B (128u * SSTR * 2u)       // 6144 B
#define STG_B  (3u * TILE_B)            // Ah|Bh|Bl = 18432 B
#define G_SMEM (4u * STG_B)             // 73728 B

__device__ __forceinline__ void gemm_core(
    const __half* __restrict__ Ah,
    const __half* __restrict__ Bh, const __half* __restrict__ Bl,
    float* __restrict__ C,
    __half* __restrict__ Chh, __half* __restrict__ Chl,
    int N, int K, int bm, int bn, char* smem, int mode,
    const float* __restrict__ cs, const float* __restrict__ sn, float oscale)
{
    const uint32_t sb = (uint32_t)__cvta_generic_to_shared(smem);
    const int tid = threadIdx.x;
    const int lane = tid & 31;
    const int wid = tid >> 5;
    const int wm = wid & 1;
    const int wn = wid >> 1;

    const int lrow = tid >> 1;
    const int lkc  = tid & 1;
    const __half* gah = Ah + (size_t)(bm * 128 + lrow) * K + lkc * 8;
    const __half* gbh = Bh + (size_t)(bn * 128 + lrow) * K + lkc * 8;
    const __half* gbl = Bl + (size_t)(bn * 128 + lrow) * K + lkc * 8;
    const uint32_t sOff = (uint32_t)(lrow * SSTR + lkc * 8) * 2;

    const uint32_t aLn = (uint32_t)((wm * 64 + (lane & 15)) * SSTR + (lane >> 4) * 8) * 2;
    const uint32_t bLn = (uint32_t)((wn * 32 + ((lane >> 4) << 3) + (lane & 7)) * SSTR
                                    + ((lane >> 3) & 1) * 8) * 2;

    float acc[4][4][4];
    #pragma unroll
    for (int i = 0; i < 4; i++)
        #pragma unroll
        for (int j = 0; j < 4; j++)
            #pragma unroll
            for (int r = 0; r < 4; r++) acc[i][j][r] = 0.f;

    const int T = K / 16;

    auto stage_load = [&](uint32_t st, int kt) {
        uint32_t base = sb + st * STG_B + sOff;
        CP16(base,              gah + kt * 16);
        CP16(base + TILE_B,     gbh + kt * 16);
        CP16(base + 2 * TILE_B, gbl + kt * 16);
        CP_COMMIT();
    };

    stage_load(0, 0);
    stage_load(1, 1);
    stage_load(2, 2);

    for (int t = 0; t < T; t++) {
        CP_WAIT2();
        __syncthreads();

        const uint32_t ab = sb + (uint32_t)(t & 3) * STG_B;
        const uint32_t bb = ab + TILE_B;

        uint32_t ah[4][4], bh[2][4], bl[2][4];
        #pragma unroll
        for (int mt = 0; mt < 4; mt++)
            LDSM4(ah[mt], ab + aLn + mt * (16 * SSTR * 2));
        #pragma unroll
        for (int pr = 0; pr < 2; pr++) {
            LDSM4(bh[pr], bb + bLn + pr * (16 * SSTR * 2));
            LDSM4(bl[pr], bb + TILE_B + bLn + pr * (16 * SSTR * 2));
        }

        if (t + 3 < T) stage_load((uint32_t)((t + 3) & 3), t + 3);
        else           CP_COMMIT();

        #pragma unroll
        for (int mt = 0; mt < 4; mt++)
            #pragma unroll
            for (int nt = 0; nt < 4; nt++) {
                const int pr = nt >> 1, q = (nt & 1) * 2;
                MMAF16(acc[mt][nt], ah[mt], bh[pr][q], bh[pr][q + 1]);
            }
        #pragma unroll
        for (int mt = 0; mt < 4; mt++)
            #pragma unroll
            for (int nt = 0; nt < 4; nt++) {
                const int pr = nt >> 1, q = (nt & 1) * 2;
                MMAF16(acc[mt][nt], ah[mt], bl[pr][q], bl[pr][q + 1]);
            }
    }

    if (mode == 0) {
        #pragma unroll
        for (int mt = 0; mt < 4; mt++) {
            const int r0 = bm * 128 + wm * 64 + mt * 16 + (lane >> 2);
            #pragma unroll
            for (int nt = 0; nt < 4; nt++) {
                const int c0 = bn * 128 + wn * 32 + nt * 8 + (lane & 3) * 2;
                *(float2*)&C[(size_t)r0 * N + c0] =
                    make_float2(acc[mt][nt][0], acc[mt][nt][1]);
                *(float2*)&C[(size_t)(r0 + 8) * N + c0] =
                    make_float2(acc[mt][nt][2], acc[mt][nt][3]);
            }
        }
    } else if (mode == 1) {
        #pragma unroll
        for (int mt = 0; mt < 4; mt++) {
            const int r0 = bm * 128 + wm * 64 + mt * 16 + (lane >> 2);
            #pragma unroll
            for (int nt = 0; nt < 4; nt++) {
                const int c0 = bn * 128 + wn * 32 + nt * 8 + (lane & 3) * 2;
                #pragma unroll
                for (int hf = 0; hf < 2; hf++) {
                    __half2 hh = __floats2half2_rn(acc[mt][nt][hf * 2],
                                                   acc[mt][nt][hf * 2 + 1]);
                    *(uint32_t*)&Chh[(size_t)(r0 + hf * 8) * N + c0] =
                        *(uint32_t*)&hh;
                }
            }
        }
    } else {
        // mode 2: rope + rmsnorm (+oscale) fused epilogue -> fp16 hi (+lo)
        CP_WAIT0();
        __syncthreads();
        float* st = (float*)smem;
        #pragma unroll
        for (int mt = 0; mt < 4; mt++) {
            const int r0 = wm * 64 + mt * 16 + (lane >> 2);
            #pragma unroll
            for (int nt = 0; nt < 4; nt++) {
                const int c0 = wn * 32 + nt * 8 + (lane & 3) * 2;
                *(float2*)&st[r0 * 132 + c0] =
                    make_float2(acc[mt][nt][0], acc[mt][nt][1]);
                *(float2*)&st[(r0 + 8) * 132 + c0] =
                    make_float2(acc[mt][nt][2], acc[mt][nt][3]);
            }
        }
        __syncthreads();

        const int cb = bn * 128;
        for (int rr = 0; rr < 16; rr++) {
            int r = wid * 16 + rr;
            int grow_ = bm * 128 + r;
            int s = grow_ & (S_ - 1);
            float x1a = st[r * 132 + lane];
            float x1b = st[r * 132 + lane + 32];
            float x2a = st[r * 132 + lane + 64], x2b = st[r * 132 + lane + 96];
            float ca = cs[s * 64 + lane], cbv = cs[s * 64 + lane + 32];
            float sa = sn[s * 64 + lane], sbv = sn[s * 64 + lane + 32];

            float o1a =  x1a * ca  + x2a * sa;
            float o1b =  x1b * cbv + x2b * sbv;
            float o2a = -x1a * sa  + x2a * ca;
            float o2b = -x1b * sbv + x2b * cbv;

            float ss = o1a * o1a + o1b * o1b + o2a * o2a + o2b * o2b;
            #pragma unroll
            for (int o = 16; o; o >>= 1) ss += __shfl_xor_sync(0xffffffffu, ss, o);
            float scale = rsqrtf(ss * (1.f / 128.f) + 1.1920928955078125e-07f)
                        * oscale;

            float v4[4] = {o1a * scale, o1b * scale, o2a * scale, o2b * scale};
            size_t gb = (size_t)grow_ * N + cb + lane;
            #pragma unroll
            for (int u = 0; u < 4; u++) {
                __half hh = __float2half(v4[u]);
                Chh[gb + u * 32] = hh;
                if (Chl) Chl[gb + u * 32] =
                    __float2half(v4[u] - __half2float(hh));
            }
        }
    }
}

// Fused Q/K/V projection + rope/rms epilogue (Q: hi scaled, K: hi+lo); V: hi.
__global__ __launch_bounds__(256, 2) void gemm_qkv(
    const __half* __restrict__ xh,
    const __half* __restrict__ wqh, const __half* __restrict__ wql,
    const __half* __restrict__ wkh, const __half* __restrict__ wkl,
    const __half* __restrict__ wvh, const __half* __restrict__ wvl,
    __half* __restrict__ qh, __half* __restrict__ kh, __half* __restrict__ kl,
    __half* __restrict__ vh,
    const float* __restrict__ cosp, const float* __restrict__ sinp)
{
    extern __shared__ char smem[];
    const int bx = blockIdx.x;
    if (bx < 16) {
        gemm_core(xh, wqh, wql, nullptr, qh, nullptr,
                  H_ * D_, E_, blockIdx.y, bx, smem, 2, cosp, sinp, QSCALE);
    } else if (bx < 20) {
        gemm_core(xh, wkh, wkl, nullptr, kh, kl,
                  KV_ * D_, E_, blockIdx.y, bx - 16, smem, 2, cosp, sinp, 1.f);
    } else {
        gemm_core(xh, wvh, wvl, nullptr, vh, nullptr,
                  KV_ * D_, E_, blockIdx.y, bx - 20, smem, 1, nullptr, nullptr, 1.f);
    }
}

__global__ __launch_bounds__(256, 2) void gemm_one(
    const __half* __restrict__ Ah,
    const __half* __restrict__ Bh, const __half* __restrict__ Bl,
    float* __restrict__ C, int N, int K)
{
    extern __shared__ char smem[];
    gemm_core(Ah, Bh, Bl, C, nullptr, nullptr, N, K,
              blockIdx.y, blockIdx.x, smem, 0, nullptr, nullptr, 1.f);
}

// ---------------------------------------------------------------------------
// fp16 2-pass sliding-window flash attention; softmax in base-2.
// 1 CTA/SM, uncapped registers (R11-proven configuration).
// ---------------------------------------------------------------------------
#define RB 17408   // 64 rows * 272 B (stride 136 fp16)
#define A_SMEM (6u * RB)

__global__ __launch_bounds__(256) void attn_mma(
    const __half* __restrict__ q_, const __half* __restrict__ kh_,
    const __half* __restrict__ kl_, const __half* __restrict__ vh_,
    __half* __restrict__ chi)
{
    extern __shared__ char smem[];
    const uint32_t sbase = (uint32_t)__cvta_generic_to_shared(smem);

    const int tid = threadIdx.x, lane = tid & 31, w = tid >> 5;
    const int q0 = blockIdx.x * 128;
    const int h  = blockIdx.y, b = blockIdx.z;
    const int kvh = h >> 2;

    {
        int r = tid >> 1;
        size_t gbase = ((size_t)(b * S_ + q0 + r)) * (H_ * D_) + h * D_;
        const uint4* gq = (const uint4*)(q_ + gbase);
        #pragma unroll
        for (int u = 0; u < 8; u++) {
            int c = (tid & 1) * 8 + u;
            *(uint4*)(smem + (size_t)r * 272 + c * 16) = gq[c];
        }
    }
    __syncthreads();

    uint32_t ah[8][4];
    {
        uint32_t qro = (uint32_t)((w * 16 + (lane & 15)) * 272);
        #pragma unroll
        for (int d = 0; d < 8; d++) {
            uint32_t co = (uint32_t)((d * 16 + (lane >> 4) * 8) * 2);
            LDSM4(ah[d], sbase + qro + co);
        }
    }
    __syncthreads();

    float pacc[16][4];
    #pragma unroll
    for (int g = 0; g < 16; g++)
        #pragma unroll
        for (int r = 0; r < 4; r++) pacc[g][r] = 0.f;

    float m_run0 = -1e30f, m_run1 = -1e30f, l0 = 0.f, l1 = 0.f;

    const int ibase = q0 + w * 16;
    const int i0 = ibase + (lane >> 2);
    const int i1 = i0 + 8;

    int t0 = q0 - 1024; if (t0 < 0) t0 = 0;
    const int n = (q0 + 128 - t0) >> 6;

    const int crow = tid >> 2;
    const size_t grow = ((size_t)b * S_) * (KV_ * D_) + (size_t)kvh * D_;

    {
        size_t gb = grow + (size_t)(t0 + crow) * (KV_ * D_);
        #pragma unroll
        for (int u = 0; u < 4; u++) {
            int c = (tid & 3) * 4 + u;
            uint32_t so = (uint32_t)(crow * 272 + c * 16);
            CP16(sbase + so,          kh_ + gb + c * 8);
            CP16(sbase + RB + so,     kl_ + gb + c * 8);
            CP16(sbase + 2 * RB + so, vh_ + gb + c * 8);
        }
        CP_COMMIT();
    }

    for (int it = 0; it < n; it++) {
        const int t = t0 + it * 64;
        if (it + 1 < n) {
            uint32_t st = (uint32_t)((it + 1) & 1) * 3 * RB;
            size_t gb = grow + (size_t)(t + 64 + crow) * (KV_ * D_);
            #pragma unroll
            for (int u = 0; u < 4; u++) {
                int c = (tid & 3) * 4 + u;
                uint32_t so = st + (uint32_t)(crow * 272 + c * 16);
                CP16(sbase + so,          kh_ + gb + c * 8);
                CP16(sbase + RB + so,     kl_ + gb + c * 8);
                CP16(sbase + 2 * RB + so, vh_ + gb + c * 8);
            }
            CP_COMMIT();
            CP_WAIT1();
        } else {
            CP_WAIT0();
        }
        __syncthreads();

        const uint32_t khb = sbase + (uint32_t)(it & 1) * 3 * RB;
        const uint32_t klb = khb + RB;
        const uint32_t vhb = khb + 2 * RB;

        float sacc[8][4];
        #pragma unroll
        for (int g = 0; g < 8; g++)
            #pragma unroll
            for (int r = 0; r < 4; r++) sacc[g][r] = 0.f;

        #pragma unroll
        for (int d = 0; d < 8; d++) {
            uint32_t co = (uint32_t)((d * 16 + ((lane >> 3) & 1) * 8) * 2);
            #pragma unroll
            for (int g = 0; g < 4; g++) {
                uint32_t ro = (uint32_t)((g * 16 + ((lane >> 4) << 3) + (lane & 7)) * 272);
                uint32_t k4h[4], k4l[4];
                LDSM4(k4h, khb + ro + co);
                LDSM4(k4l, klb + ro + co);
                MMAF16(sacc[2 * g],     ah[d], k4h[0], k4h[1]);
                MMAF16(sacc[2 * g],     ah[d], k4l[0], k4l[1]);
                MMAF16(sacc[2 * g + 1], ah[d], k4h[2], k4h[3]);
                MMAF16(sacc[2 * g + 1], ah[d], k4l[2], k4l[3]);
            }
        }

        const bool need_mask = (t + 63 >= ibase) || (t + 1009 <= ibase);
        float m0 = -INFINITY, m1 = -INFINITY;
        #pragma unroll
        for (int g = 0; g < 8; g++) {
            float s0 = sacc[g][0], s1 = sacc[g][1];
            float s2 = sacc[g][2], s3 = sacc[g][3];
            if (need_mask) {
                int jb = t + g * 8 + 2 * (lane & 3);
                s0 = ((jb     <= i0) && (i0 - jb < 1024))     ? s0 : -INFINITY;
                s1 = ((jb + 1 <= i0) && (i0 - jb - 1 < 1024)) ? s1 : -INFINITY;
                s2 = ((jb     <= i1) && (i1 - jb < 1024))     ? s2 : -INFINITY;
                s3 = ((jb + 1 <= i1) && (i1 - jb - 1 < 1024)) ? s3 : -INFINITY;
                sacc[g][0] = s0; sacc[g][1] = s1;
                sacc[g][2] = s2; sacc[g][3] = s3;
            }
            m0 = fmaxf(m0, fmaxf(s0, s1));
            m1 = fmaxf(m1, fmaxf(s2, s3));
        }
        m0 = fmaxf(m0, __shfl_xor_sync(0xffffffffu, m0, 1));
        m0 = fmaxf(m0, __shfl_xor_sync(0xffffffffu, m0, 2));
        m1 = fmaxf(m1, __shfl_xor_sync(0xffffffffu, m1, 1));
        m1 = fmaxf(m1, __shfl_xor_sync(0xffffffffu, m1, 2));

        float mn0 = fmaxf(m_run0, m0), mn1 = fmaxf(m_run1, m1);
        float a0 = ex2f(m_run0 - mn0), a1 = ex2f(m_run1 - mn1);
        m_run0 = mn0; m_run1 = mn1;

        float rs0 = 0.f, rs1 = 0.f;
        #pragma unroll
        for (int g = 0; g < 8; g++) {
            float p0 = ex2f(sacc[g][0] - mn0);
            float p1 = ex2f(sacc[g][1] - mn0);
            float p2 = ex2f(sacc[g][2] - mn1);
            float p3 = ex2f(sacc[g][3] - mn1);
            sacc[g][0] = p0; sacc[g][1] = p1; sacc[g][2] = p2; sacc[g][3] = p3;
            rs0 += p0 + p1; rs1 += p2 + p3;
        }
        rs0 += __shfl_xor_sync(0xffffffffu, rs0, 1);
        rs0 += __shfl_xor_sync(0xffffffffu, rs0, 2);
        rs1 += __shfl_xor_sync(0xffffffffu, rs1, 1);
        rs1 += __shfl_xor_sync(0xffffffffu, rs1, 2);
        l0 = l0 * a0 + rs0;
        l1 = l1 * a1 + rs1;

        #pragma unroll
        for (int g = 0; g < 16; g++) {
            pacc[g][0] *= a0; pacc[g][1] *= a0;
            pacc[g][2] *= a1; pacc[g][3] *= a1;
        }

        // per-kt P conversion + PV
        #pragma unroll
        for (int kt = 0; kt < 4; kt++) {
            uint32_t ph[4], pl[4];
            #pragma unroll
            for (int qq = 0; qq < 2; qq++) {
                #pragma unroll
                for (int r2 = 0; r2 < 2; r2++) {
                    float x0 = sacc[2 * kt + qq][r2 * 2];
                    float x1 = sacc[2 * kt + qq][r2 * 2 + 1];
                    __half2 hh = __floats2half2_rn(x0, x1);
                    __half2 ll = __floats2half2_rn(
                        x0 - __half2float(hh.x), x1 - __half2float(hh.y));
                    ph[qq * 2 + r2] = *(uint32_t*)&hh;
                    pl[qq * 2 + r2] = *(uint32_t*)&ll;
                }
            }
            uint32_t ro = (uint32_t)((kt * 16 + (lane & 15)) * 272);
            uint32_t co = (uint32_t)(((lane >> 4) * 8) * 2);
            #pragma unroll
            for (int g = 0; g < 8; g++) {
                uint32_t v4h[4];
                LDSM4T(v4h, vhb + ro + co + g * 32);
                MMAF16(pacc[2 * g],     ph, v4h[0], v4h[1]);
                MMAF16(pacc[2 * g],     pl, v4h[0], v4h[1]);
                MMAF16(pacc[2 * g + 1], ph, v4h[2], v4h[3]);
                MMAF16(pacc[2 * g + 1], pl, v4h[2], v4h[3]);
            }
        }
        __syncthreads();
    }

    float inv0 = 1.f / l0, inv1 = 1.f / l1;
    size_t base0 = ((size_t)(b * S_ + i0)) * (H_ * D_) + h * D_;
    size_t base1 = base0 + (size_t)8 * (H_ * D_);
    #pragma unroll
    for (int g = 0; g < 16; g++) {
        int col = g * 8 + 2 * (lane & 3);
        __half2 h0 = __floats2half2_rn(pacc[g][0] * inv0, pacc[g][1] * inv0);
        __half2 h1 = __floats2half2_rn(pacc[g][2] * inv1, pacc[g][3] * inv1);
        *(uint32_t*)&chi[base0 + col] = *(uint32_t*)&h0;
        *(uint32_t*)&chi[base1 + col] = *(uint32_t*)&h1;
    }
}

// ---------------------------------------------------------------------------
extern "C" void kernel_launch(void* const* d_in, const int* in_sizes, int n_in,
                              void* d_out, int out_size)
{
    const float* x    = (const float*)d_in[0];
    const float* cosp = (const float*)d_in[1];
    const float* sinp = (const float*)d_in[2];
    const float* Wq   = (const float*)d_in[3];
    const float* Wk   = (const float*)d_in[4];
    const float* Wv   = (const float*)d_in[5];
    const float* Wo   = (const float*)d_in[6];
    float* out = (float*)d_out;

    __half *xhi, *wqhi, *wqlo, *wkhi, *wklo, *wvhi, *wvlo, *wohi, *wolo;
    __half *chi, *qh, *kh, *kl, *vh;
    cudaGetSymbolAddress((void**)&xhi, g_xhi);
    cudaGetSymbolAddress((void**)&wqhi, g_wqhi);
    cudaGetSymbolAddress((void**)&wqlo, g_wqlo);
    cudaGetSymbolAddress((void**)&wkhi, g_wkhi);
    cudaGetSymbolAddress((void**)&wklo, g_wklo);
    cudaGetSymbolAddress((void**)&wvhi, g_wvhi);
    cudaGetSymbolAddress((void**)&wvlo, g_wvlo);
    cudaGetSymbolAddress((void**)&wohi, g_wohi);
    cudaGetSymbolAddress((void**)&wolo, g_wolo);
    cudaGetSymbolAddress((void**)&chi, g_chi);
    cudaGetSymbolAddress((void**)&qh, g_qh);
    cudaGetSymbolAddress((void**)&kh, g_kh);
    cudaGetSymbolAddress((void**)&kl, g_kl);
    cudaGetSymbolAddress((void**)&vh, g_vh);

    static bool attr_done = false;
    if (!attr_done) {
        cudaFuncSetAttribute(attn_mma,
            cudaFuncAttributeMaxDynamicSharedMemorySize, A_SMEM);
        cudaFuncSetAttribute(gemm_qkv,
            cudaFuncAttributeMaxDynamicSharedMemorySize, G_SMEM);
        cudaFuncSetAttribute(gemm_one,
            cudaFuncAttributeMaxDynamicSharedMemorySize, G_SMEM);
        attr_done = true;
    }

    const int M = B_ * S_;

    // fused split (4 float2 per thread; x hi-only)
    {
        size_t blocks = (N2_ALL / 4 + 255) / 256;
        split_all<<<(unsigned)blocks, 256>>>(
            (const float2*)x, (const float2*)Wq, (const float2*)Wk,
            (const float2*)Wv, (const float2*)Wo,
            (__half2*)xhi,
            (__half2*)wqhi, (__half2*)wqlo,
            (__half2*)wkhi, (__half2*)wklo,
            (__half2*)wvhi, (__half2*)wvlo,
            (__half2*)wohi, (__half2*)wolo);
    }

    // fused Q/K/V projections + rope/rms epilogue
    gemm_qkv<<<dim3(24, M / 128), 256, G_SMEM>>>(
        xhi, wqhi, wqlo, wkhi, wklo, wvhi, wvlo,
        qh, kh, kl, vh, cosp, sinp);

    // attention (1 CTA/SM, uncapped regs)
    attn_mma<<<dim3(S_ / 128, H_, B_), 256, A_SMEM>>>(
        qh, kh, kl, vh, chi);

    // output projection
    gemm_one<<<dim3(E_ / 128, M / 128), 256, G_SMEM>>>(
        chi, wohi, wolo, out, E_, E_);
}

// round 15
// speedup vs baseline: 1.0935x; 1.0157x over previous
#include <cuda_runtime.h>
#include <cuda_bf16.h>
#include <cuda_fp16.h>
#include <math.h>
#include <stdint.h>

#define B_  2
#define S_  2048
#define E_  2048
#define H_  16
#define KV_ 4
#define D_  128
#define WIN_ 1024

// fp16 scratch
__device__ __half g_xhi[(size_t)B_ * S_ * E_];
__device__ __half g_wqhi[(size_t)H_ * D_ * E_];
__device__ __half g_wqlo[(size_t)H_ * D_ * E_];
__device__ __half g_wkhi[(size_t)KV_ * D_ * E_];
__device__ __half g_wklo[(size_t)KV_ * D_ * E_];
__device__ __half g_wvhi[(size_t)KV_ * D_ * E_];
__device__ __half g_wvlo[(size_t)KV_ * D_ * E_];
__device__ __half g_wohi[(size_t)E_ * H_ * D_];
__device__ __half g_wolo[(size_t)E_ * H_ * D_];
__device__ __half g_chi[(size_t)B_ * S_ * H_ * D_];

// fp16 attention operands
__device__ __half g_qh[(size_t)B_ * S_ * H_ * D_];
__device__ __half g_kh[(size_t)B_ * S_ * KV_ * D_];
__device__ __half g_kl[(size_t)B_ * S_ * KV_ * D_];
__device__ __half g_vh[(size_t)B_ * S_ * KV_ * D_];

// Q pre-scale: D^-0.5 * log2(e)  (softmax done in base-2)
#define QSCALE 0.12752820723310574f

// ---------------------------------------------------------------------------
// Fused fp16 splitter, 4 float2 per thread. x: hi only; weights: hi+lo.
// ---------------------------------------------------------------------------
#define N2_X  ((size_t)B_ * S_ * E_ / 2)
#define N2_WQ ((size_t)H_ * D_ * E_ / 2)
#define N2_WK ((size_t)KV_ * D_ * E_ / 2)
#define N2_ALL (N2_X + 2 * N2_WQ + 2 * N2_WK)

__global__ __launch_bounds__(256) void split_all(
    const float2* __restrict__ x,  const float2* __restrict__ wq,
    const float2* __restrict__ wk, const float2* __restrict__ wv,
    const float2* __restrict__ wo,
    __half2* __restrict__ xhi,
    __half2* __restrict__ qhi,  __half2* __restrict__ qlo,
    __half2* __restrict__ khi,  __half2* __restrict__ klo,
    __half2* __restrict__ vhi,  __half2* __restrict__ vlo,
    __half2* __restrict__ ohi,  __half2* __restrict__ olo)
{
    size_t g = ((size_t)blockIdx.x * blockDim.x + threadIdx.x) * 4;
    if (g >= N2_ALL) return;

    const float2* src;
    __half2 *dh, *dl;
    size_t off = g;
    if (off < N2_X)                    { src = x;  dh = xhi; dl = nullptr; }
    else if ((off -= N2_X) < N2_WQ)    { src = wq; dh = qhi; dl = qlo; }
    else if ((off -= N2_WQ) < N2_WK)   { src = wk; dh = khi; dl = klo; }
    else if ((off -= N2_WK) < N2_WK)   { src = wv; dh = vhi; dl = vlo; }
    else { off -= N2_WK;                 src = wo; dh = ohi; dl = olo; }

    float2 vv[4] = {src[off], src[off + 1], src[off + 2], src[off + 3]};
    #pragma unroll
    for (int u = 0; u < 4; u++) {
        __half h0 = __float2half(vv[u].x);
        __half h1 = __float2half(vv[u].y);
        __half2 hh; hh.x = h0; hh.y = h1;
        dh[off + u] = hh;
        if (dl) {
            __half2 ll;
            ll.x = __float2half(vv[u].x - __half2float(h0));
            ll.y = __float2half(vv[u].y - __half2float(h1));
            dl[off + u] = ll;
        }
    }
}

// ---------------------------------------------------------------------------
// PTX helpers
// ---------------------------------------------------------------------------
#define CP16(dst, src) \
    asm volatile("cp.async.cg.shared.global [%0], [%1], 16;\n" :: "r"(dst), "l"(src))
#define CP_COMMIT() asm volatile("cp.async.commit_group;\n" ::)
#define CP_WAIT2()  asm volatile("cp.async.wait_group 2;\n" ::)
#define CP_WAIT1()  asm volatile("cp.async.wait_group 1;\n" ::)
#define CP_WAIT0()  asm volatile("cp.async.wait_group 0;\n" ::)

#define LDSM4(R, addr) \
    asm volatile("ldmatrix.sync.aligned.m8n8.x4.shared.b16 {%0,%1,%2,%3}, [%4];\n" \
        : "=r"(R[0]), "=r"(R[1]), "=r"(R[2]), "=r"(R[3]) : "r"(addr))
#define LDSM4T(R, addr) \
    asm volatile("ldmatrix.sync.aligned.m8n8.x4.trans.shared.b16 {%0,%1,%2,%3}, [%4];\n" \
        : "=r"(R[0]), "=r"(R[1]), "=r"(R[2]), "=r"(R[3]) : "r"(addr))

#define MMAF16(acc, a, b0, b1) \
    asm volatile("mma.sync.aligned.m16n8k16.row.col.f32.f16.f16.f32 " \
        "{%0,%1,%2,%3}, {%4,%5,%6,%7}, {%8,%9}, {%0,%1,%2,%3};\n" \
        : "+f"(acc[0]), "+f"(acc[1]), "+f"(acc[2]), "+f"(acc[3]) \
        : "r"(a[0]), "r"(a[1]), "r"(a[2]), "r"(a[3]), "r"(b0), "r"(b1))

__device__ __forceinline__ float ex2f(float x) {
    float r;
    asm("ex2.approx.f32 %0, %1;" : "=f"(r) : "f"(x));
    return r;
}

// ---------------------------------------------------------------------------
// GEMM core (fp16 2-pass): C = Ah@Bh^T + Ah@Bl^T   (fp32 accum)
// 4-stage cp.async pipeline, 1 barrier/K16, 2 CTAs/SM.
// mode 0: fp32 out. mode 1: fp16 hi out. mode 2: rope+rms*oscale -> fp16.
// ---------------------------------------------------------------------------
#define SSTR   24
#define TILE_B (128u * SSTR * 2u)       // 6144 B
#define STG_B  (3u * TILE_B)            // Ah|Bh|Bl = 18432 B
#define G_SMEM (4u * STG_B)             // 73728 B

__device__ __forceinline__ void gemm_core(
    const __half* __restrict__ Ah,
    const __half* __restrict__ Bh, const __half* __restrict__ Bl,
    float* __restrict__ C,
    __half* __restrict__ Chh, __half* __restrict__ Chl,
    int N, int K, int bm, int bn, char* smem, int mode,
    const float* __restrict__ cs, const float* __restrict__ sn, float oscale)
{
    const uint32_t sb = (uint32_t)__cvta_generic_to_shared(smem);
    const int tid = threadIdx.x;
    const int lane = tid & 31;
    const int wid = tid >> 5;
    const int wm = wid & 1;
    const int wn = wid >> 1;

    const int lrow = tid >> 1;
    const int lkc  = tid & 1;
    const __half* gah = Ah + (size_t)(bm * 128 + lrow) * K + lkc * 8;
    const __half* gbh = Bh + (size_t)(bn * 128 + lrow) * K + lkc * 8;
    const __half* gbl = Bl + (size_t)(bn * 128 + lrow) * K + lkc * 8;
    const uint32_t sOff = (uint32_t)(lrow * SSTR + lkc * 8) * 2;

    const uint32_t aLn = (uint32_t)((wm * 64 + (lane & 15)) * SSTR + (lane >> 4) * 8) * 2;
    const uint32_t bLn = (uint32_t)((wn * 32 + ((lane >> 4) << 3) + (lane & 7)) * SSTR
                                    + ((lane >> 3) & 1) * 8) * 2;

    float acc[4][4][4];
    #pragma unroll
    for (int i = 0; i < 4; i++)
        #pragma unroll
        for (int j = 0; j < 4; j++)
            #pragma unroll
            for (int r = 0; r < 4; r++) acc[i][j][r] = 0.f;

    const int T = K / 16;

    auto stage_load = [&](uint32_t st, int kt) {
        uint32_t base = sb + st * STG_B + sOff;
        CP16(base,              gah + kt * 16);
        CP16(base + TILE_B,     gbh + kt * 16);
        CP16(base + 2 * TILE_B, gbl + kt * 16);
        CP_COMMIT();
    };

    stage_load(0, 0);
    stage_load(1, 1);
    stage_load(2, 2);

    for (int t = 0; t < T; t++) {
        CP_WAIT2();
        __syncthreads();

        const uint32_t ab = sb + (uint32_t)(t & 3) * STG_B;
        const uint32_t bb = ab + TILE_B;

        uint32_t ah[4][4], bh[2][4], bl[2][4];
        #pragma unroll
        for (int mt = 0; mt < 4; mt++)
            LDSM4(ah[mt], ab + aLn + mt * (16 * SSTR * 2));
        #pragma unroll
        for (int pr = 0; pr < 2; pr++) {
            LDSM4(bh[pr], bb + bLn + pr * (16 * SSTR * 2));
            LDSM4(bl[pr], bb + TILE_B + bLn + pr * (16 * SSTR * 2));
        }

        if (t + 3 < T) stage_load((uint32_t)((t + 3) & 3), t + 3);
        else           CP_COMMIT();

        #pragma unroll
        for (int mt = 0; mt < 4; mt++)
            #pragma unroll
            for (int nt = 0; nt < 4; nt++) {
                const int pr = nt >> 1, q = (nt & 1) * 2;
                MMAF16(acc[mt][nt], ah[mt], bh[pr][q], bh[pr][q + 1]);
            }
        #pragma unroll
        for (int mt = 0; mt < 4; mt++)
            #pragma unroll
            for (int nt = 0; nt < 4; nt++) {
                const int pr = nt >> 1, q = (nt & 1) * 2;
                MMAF16(acc[mt][nt], ah[mt], bl[pr][q], bl[pr][q + 1]);
            }
    }

    if (mode == 0) {
        #pragma unroll
        for (int mt = 0; mt < 4; mt++) {
            const int r0 = bm * 128 + wm * 64 + mt * 16 + (lane >> 2);
            #pragma unroll
            for (int nt = 0; nt < 4; nt++) {
                const int c0 = bn * 128 + wn * 32 + nt * 8 + (lane & 3) * 2;
                *(float2*)&C[(size_t)r0 * N + c0] =
                    make_float2(acc[mt][nt][0], acc[mt][nt][1]);
                *(float2*)&C[(size_t)(r0 + 8) * N + c0] =
                    make_float2(acc[mt][nt][2], acc[mt][nt][3]);
            }
        }
    } else if (mode == 1) {
        #pragma unroll
        for (int mt = 0; mt < 4; mt++) {
            const int r0 = bm * 128 + wm * 64 + mt * 16 + (lane >> 2);
            #pragma unroll
            for (int nt = 0; nt < 4; nt++) {
                const int c0 = bn * 128 + wn * 32 + nt * 8 + (lane & 3) * 2;
                #pragma unroll
                for (int hf = 0; hf < 2; hf++) {
                    __half2 hh = __floats2half2_rn(acc[mt][nt][hf * 2],
                                                   acc[mt][nt][hf * 2 + 1]);
                    *(uint32_t*)&Chh[(size_t)(r0 + hf * 8) * N + c0] =
                        *(uint32_t*)&hh;
                }
            }
        }
    } else {
        // mode 2: rope + rmsnorm (+oscale) fused epilogue -> fp16 hi (+lo)
        CP_WAIT0();
        __syncthreads();
        float* st = (float*)smem;
        #pragma unroll
        for (int mt = 0; mt < 4; mt++) {
            const int r0 = wm * 64 + mt * 16 + (lane >> 2);
            #pragma unroll
            for (int nt = 0; nt < 4; nt++) {
                const int c0 = wn * 32 + nt * 8 + (lane & 3) * 2;
                *(float2*)&st[r0 * 132 + c0] =
                    make_float2(acc[mt][nt][0], acc[mt][nt][1]);
                *(float2*)&st[(r0 + 8) * 132 + c0] =
                    make_float2(acc[mt][nt][2], acc[mt][nt][3]);
            }
        }
        __syncthreads();

        const int cb = bn * 128;
        for (int rr = 0; rr < 16; rr++) {
            int r = wid * 16 + rr;
            int grow_ = bm * 128 + r;
            int s = grow_ & (S_ - 1);
            float x1a = st[r * 132 + lane];
            float x1b = st[r * 132 + lane + 32];
            float x2a = st[r * 132 + lane + 64], x2b = st[r * 132 + lane + 96];
            float ca = cs[s * 64 + lane], cbv = cs[s * 64 + lane + 32];
            float sa = sn[s * 64 + lane], sbv = sn[s * 64 + lane + 32];

            float o1a =  x1a * ca  + x2a * sa;
            float o1b =  x1b * cbv + x2b * sbv;
            float o2a = -x1a * sa  + x2a * ca;
            float o2b = -x1b * sbv + x2b * cbv;

            float ss = o1a * o1a + o1b * o1b + o2a * o2a + o2b * o2b;
            #pragma unroll
            for (int o = 16; o; o >>= 1) ss += __shfl_xor_sync(0xffffffffu, ss, o);
            float scale = rsqrtf(ss * (1.f / 128.f) + 1.1920928955078125e-07f)
                        * oscale;

            float v4[4] = {o1a * scale, o1b * scale, o2a * scale, o2b * scale};
            size_t gb = (size_t)grow_ * N + cb + lane;
            #pragma unroll
            for (int u = 0; u < 4; u++) {
                __half hh = __float2half(v4[u]);
                Chh[gb + u * 32] = hh;
                if (Chl) Chl[gb + u * 32] =
                    __float2half(v4[u] - __half2float(hh));
            }
        }
    }
}

// Fused Q/K/V projection + rope/rms epilogue (Q: hi scaled, K: hi+lo); V: hi.
__global__ __launch_bounds__(256, 2) void gemm_qkv(
    const __half* __restrict__ xh,
    const __half* __restrict__ wqh, const __half* __restrict__ wql,
    const __half* __restrict__ wkh, const __half* __restrict__ wkl,
    const __half* __restrict__ wvh, const __half* __restrict__ wvl,
    __half* __restrict__ qh, __half* __restrict__ kh, __half* __restrict__ kl,
    __half* __restrict__ vh,
    const float* __restrict__ cosp, const float* __restrict__ sinp)
{
    extern __shared__ char smem[];
    const int bx = blockIdx.x;
    if (bx < 16) {
        gemm_core(xh, wqh, wql, nullptr, qh, nullptr,
                  H_ * D_, E_, blockIdx.y, bx, smem, 2, cosp, sinp, QSCALE);
    } else if (bx < 20) {
        gemm_core(xh, wkh, wkl, nullptr, kh, kl,
                  KV_ * D_, E_, blockIdx.y, bx - 16, smem, 2, cosp, sinp, 1.f);
    } else {
        gemm_core(xh, wvh, wvl, nullptr, vh, nullptr,
                  KV_ * D_, E_, blockIdx.y, bx - 20, smem, 1, nullptr, nullptr, 1.f);
    }
}

__global__ __launch_bounds__(256, 2) void gemm_one(
    const __half* __restrict__ Ah,
    const __half* __restrict__ Bh, const __half* __restrict__ Bl,
    float* __restrict__ C, int N, int K)
{
    extern __shared__ char smem[];
    gemm_core(Ah, Bh, Bl, C, nullptr, nullptr, N, K,
              blockIdx.y, blockIdx.x, smem, 0, nullptr, nullptr, 1.f);
}

// ---------------------------------------------------------------------------
// fp16 2-pass sliding-window flash attention; softmax in base-2.
// 1 CTA/SM, uncapped registers. Heavy-first q-tile order + per-warp
// fully-masked-tile skip (tile must intersect [ibase-1023, ibase+15]).
// ---------------------------------------------------------------------------
#define RB 17408   // 64 rows * 272 B (stride 136 fp16)
#define A_SMEM (6u * RB)

__global__ __launch_bounds__(256) void attn_mma(
    const __half* __restrict__ q_, const __half* __restrict__ kh_,
    const __half* __restrict__ kl_, const __half* __restrict__ vh_,
    __half* __restrict__ chi)
{
    extern __shared__ char smem[];
    const uint32_t sbase = (uint32_t)__cvta_generic_to_shared(smem);

    const int tid = threadIdx.x, lane = tid & 31, w = tid >> 5;
    // heavy-first: high q0 (more KV tiles) launches first
    const int q0 = (gridDim.x - 1 - blockIdx.x) * 128;
    const int h  = blockIdx.y, b = blockIdx.z;
    const int kvh = h >> 2;

    {
        int r = tid >> 1;
        size_t gbase = ((size_t)(b * S_ + q0 + r)) * (H_ * D_) + h * D_;
        const uint4* gq = (const uint4*)(q_ + gbase);
        #pragma unroll
        for (int u = 0; u < 8; u++) {
            int c = (tid & 1) * 8 + u;
            *(uint4*)(smem + (size_t)r * 272 + c * 16) = gq[c];
        }
    }
    __syncthreads();

    uint32_t ah[8][4];
    {
        uint32_t qro = (uint32_t)((w * 16 + (lane & 15)) * 272);
        #pragma unroll
        for (int d = 0; d < 8; d++) {
            uint32_t co = (uint32_t)((d * 16 + (lane >> 4) * 8) * 2);
            LDSM4(ah[d], sbase + qro + co);
        }
    }
    __syncthreads();

    float pacc[16][4];
    #pragma unroll
    for (int g = 0; g < 16; g++)
        #pragma unroll
        for (int r = 0; r < 4; r++) pacc[g][r] = 0.f;

    float m_run0 = -1e30f, m_run1 = -1e30f, l0 = 0.f, l1 = 0.f;

    const int ibase = q0 + w * 16;
    const int i0 = ibase + (lane >> 2);
    const int i1 = i0 + 8;

    int t0 = q0 - 1024; if (t0 < 0) t0 = 0;
    const int n = (q0 + 128 - t0) >> 6;

    const int crow = tid >> 2;
    const size_t grow = ((size_t)b * S_) * (KV_ * D_) + (size_t)kvh * D_;

    {
        size_t gb = grow + (size_t)(t0 + crow) * (KV_ * D_);
        #pragma unroll
        for (int u = 0; u < 4; u++) {
            int c = (tid & 3) * 4 + u;
            uint32_t so = (uint32_t)(crow * 272 + c * 16);
            CP16(sbase + so,          kh_ + gb + c * 8);
            CP16(sbase + RB + so,     kl_ + gb + c * 8);
            CP16(sbase + 2 * RB + so, vh_ + gb + c * 8);
        }
        CP_COMMIT();
    }

    for (int it = 0; it < n; it++) {
        const int t = t0 + it * 64;
        if (it + 1 < n) {
            uint32_t st = (uint32_t)((it + 1) & 1) * 3 * RB;
            size_t gb = grow + (size_t)(t + 64 + crow) * (KV_ * D_);
            #pragma unroll
            for (int u = 0; u < 4; u++) {
                int c = (tid & 3) * 4 + u;
                uint32_t so = st + (uint32_t)(crow * 272 + c * 16);
                CP16(sbase + so,          kh_ + gb + c * 8);
                CP16(sbase + RB + so,     kl_ + gb + c * 8);
                CP16(sbase + 2 * RB + so, vh_ + gb + c * 8);
            }
            CP_COMMIT();
            CP_WAIT1();
        } else {
            CP_WAIT0();
        }
        __syncthreads();

        // per-warp skip: warp rows [ibase, ibase+15]; valid keys span
        // [ibase-1023, ibase+15]. Tile [t, t+63] must intersect that.
        const bool active = (t <= ibase + 15) && (t + 63 >= ibase - 1023);
        if (active) {

        const uint32_t khb = sbase + (uint32_t)(it & 1) * 3 * RB;
        const uint32_t klb = khb + RB;
        const uint32_t vhb = khb + 2 * RB;

        float sacc[8][4];
        #pragma unroll
        for (int g = 0; g < 8; g++)
            #pragma unroll
            for (int r = 0; r < 4; r++) sacc[g][r] = 0.f;

        #pragma unroll
        for (int d = 0; d < 8; d++) {
            uint32_t co = (uint32_t)((d * 16 + ((lane >> 3) & 1) * 8) * 2);
            #pragma unroll
            for (int g = 0; g < 4; g++) {
                uint32_t ro = (uint32_t)((g * 16 + ((lane >> 4) << 3) + (lane & 7)) * 272);
                uint32_t k4h[4], k4l[4];
                LDSM4(k4h, khb + ro + co);
                LDSM4(k4l, klb + ro + co);
                MMAF16(sacc[2 * g],     ah[d], k4h[0], k4h[1]);
                MMAF16(sacc[2 * g],     ah[d], k4l[0], k4l[1]);
                MMAF16(sacc[2 * g + 1], ah[d], k4h[2], k4h[3]);
                MMAF16(sacc[2 * g + 1], ah[d], k4l[2], k4l[3]);
            }
        }

        const bool need_mask = (t + 63 >= ibase) || (t + 1009 <= ibase);
        float m0 = -INFINITY, m1 = -INFINITY;
        #pragma unroll
        for (int g = 0; g < 8; g++) {
            float s0 = sacc[g][0], s1 = sacc[g][1];
            float s2 = sacc[g][2], s3 = sacc[g][3];
            if (need_mask) {
                int jb = t + g * 8 + 2 * (lane & 3);
                s0 = ((jb     <= i0) && (i0 - jb < 1024))     ? s0 : -INFINITY;
                s1 = ((jb + 1 <= i0) && (i0 - jb - 1 < 1024)) ? s1 : -INFINITY;
                s2 = ((jb     <= i1) && (i1 - jb < 1024))     ? s2 : -INFINITY;
                s3 = ((jb + 1 <= i1) && (i1 - jb - 1 < 1024)) ? s3 : -INFINITY;
                sacc[g][0] = s0; sacc[g][1] = s1;
                sacc[g][2] = s2; sacc[g][3] = s3;
            }
            m0 = fmaxf(m0, fmaxf(s0, s1));
            m1 = fmaxf(m1, fmaxf(s2, s3));
        }
        m0 = fmaxf(m0, __shfl_xor_sync(0xffffffffu, m0, 1));
        m0 = fmaxf(m0, __shfl_xor_sync(0xffffffffu, m0, 2));
        m1 = fmaxf(m1, __shfl_xor_sync(0xffffffffu, m1, 1));
        m1 = fmaxf(m1, __shfl_xor_sync(0xffffffffu, m1, 2));

        float mn0 = fmaxf(m_run0, m0), mn1 = fmaxf(m_run1, m1);
        float a0 = ex2f(m_run0 - mn0), a1 = ex2f(m_run1 - mn1);
        m_run0 = mn0; m_run1 = mn1;

        float rs0 = 0.f, rs1 = 0.f;
        #pragma unroll
        for (int g = 0; g < 8; g++) {
            float p0 = ex2f(sacc[g][0] - mn0);
            float p1 = ex2f(sacc[g][1] - mn0);
            float p2 = ex2f(sacc[g][2] - mn1);
            float p3 = ex2f(sacc[g][3] - mn1);
            sacc[g][0] = p0; sacc[g][1] = p1; sacc[g][2] = p2; sacc[g][3] = p3;
            rs0 += p0 + p1; rs1 += p2 + p3;
        }
        rs0 += __shfl_xor_sync(0xffffffffu, rs0, 1);
        rs0 += __shfl_xor_sync(0xffffffffu, rs0, 2);
        rs1 += __shfl_xor_sync(0xffffffffu, rs1, 1);
        rs1 += __shfl_xor_sync(0xffffffffu, rs1, 2);
        l0 = l0 * a0 + rs0;
        l1 = l1 * a1 + rs1;

        #pragma unroll
        for (int g = 0; g < 16; g++) {
            pacc[g][0] *= a0; pacc[g][1] *= a0;
            pacc[g][2] *= a1; pacc[g][3] *= a1;
        }

        // per-kt P conversion + PV
        #pragma unroll
        for (int kt = 0; kt < 4; kt++) {
            uint32_t ph[4], pl[4];
            #pragma unroll
            for (int qq = 0; qq < 2; qq++) {
                #pragma unroll
                for (int r2 = 0; r2 < 2; r2++) {
                    float x0 = sacc[2 * kt + qq][r2 * 2];
                    float x1 = sacc[2 * kt + qq][r2 * 2 + 1];
                    __half2 hh = __floats2half2_rn(x0, x1);
                    __half2 ll = __floats2half2_rn(
                        x0 - __half2float(hh.x), x1 - __half2float(hh.y));
                    ph[qq * 2 + r2] = *(uint32_t*)&hh;
                    pl[qq * 2 + r2] = *(uint32_t*)&ll;
                }
            }
            uint32_t ro = (uint32_t)((kt * 16 + (lane & 15)) * 272);
            uint32_t co = (uint32_t)(((lane >> 4) * 8) * 2);
            #pragma unroll
            for (int g = 0; g < 8; g++) {
                uint32_t v4h[4];
                LDSM4T(v4h, vhb + ro + co + g * 32);
                MMAF16(pacc[2 * g],     ph, v4h[0], v4h[1]);
                MMAF16(pacc[2 * g],     pl, v4h[0], v4h[1]);
                MMAF16(pacc[2 * g + 1], ph, v4h[2], v4h[3]);
                MMAF16(pacc[2 * g + 1], pl, v4h[2], v4h[3]);
            }
        }

        } // active
        __syncthreads();
    }

    float inv0 = 1.f / l0, inv1 = 1.f / l1;
    size_t base0 = ((size_t)(b * S_ + i0)) * (H_ * D_) + h * D_;
    size_t base1 = base0 + (size_t)8 * (H_ * D_);
    #pragma unroll
    for (int g = 0; g < 16; g++) {
        int col = g * 8 + 2 * (lane & 3);
        __half2 h0 = __floats2half2_rn(pacc[g][0] * inv0, pacc[g][1] * inv0);
        __half2 h1 = __floats2half2_rn(pacc[g][2] * inv1, pacc[g][3] * inv1);
        *(uint32_t*)&chi[base0 + col] = *(uint32_t*)&h0;
        *(uint32_t*)&chi[base1 + col] = *(uint32_t*)&h1;
    }
}

// ---------------------------------------------------------------------------
extern "C" void kernel_launch(void* const* d_in, const int* in_sizes, int n_in,
                              void* d_out, int out_size)
{
    const float* x    = (const float*)d_in[0];
    const float* cosp = (const float*)d_in[1];
    const float* sinp = (const float*)d_in[2];
    const float* Wq   = (const float*)d_in[3];
    const float* Wk   = (const float*)d_in[4];
    const float* Wv   = (const float*)d_in[5];
    const float* Wo   = (const float*)d_in[6];
    float* out = (float*)d_out;

    __half *xhi, *wqhi, *wqlo, *wkhi, *wklo, *wvhi, *wvlo, *wohi, *wolo;
    __half *chi, *qh, *kh, *kl, *vh;
    cudaGetSymbolAddress((void**)&xhi, g_xhi);
    cudaGetSymbolAddress((void**)&wqhi, g_wqhi);
    cudaGetSymbolAddress((void**)&wqlo, g_wqlo);
    cudaGetSymbolAddress((void**)&wkhi, g_wkhi);
    cudaGetSymbolAddress((void**)&wklo, g_wklo);
    cudaGetSymbolAddress((void**)&wvhi, g_wvhi);
    cudaGetSymbolAddress((void**)&wvlo, g_wvlo);
    cudaGetSymbolAddress((void**)&wohi, g_wohi);
    cudaGetSymbolAddress((void**)&wolo, g_wolo);
    cudaGetSymbolAddress((void**)&chi, g_chi);
    cudaGetSymbolAddress((void**)&qh, g_qh);
    cudaGetSymbolAddress((void**)&kh, g_kh);
    cudaGetSymbolAddress((void**)&kl, g_kl);
    cudaGetSymbolAddress((void**)&vh, g_vh);

    static bool attr_done = false;
    if (!attr_done) {
        cudaFuncSetAttribute(attn_mma,
            cudaFuncAttributeMaxDynamicSharedMemorySize, A_SMEM);
        cudaFuncSetAttribute(gemm_qkv,
            cudaFuncAttributeMaxDynamicSharedMemorySize, G_SMEM);
        cudaFuncSetAttribute(gemm_one,
            cudaFuncAttributeMaxDynamicSharedMemorySize, G_SMEM);
        attr_done = true;
    }

    const int M = B_ * S_;

    // fused split (4 float2 per thread; x hi-only)
    {
        size_t blocks = (N2_ALL / 4 + 255) / 256;
        split_all<<<(unsigned)blocks, 256>>>(
            (const float2*)x, (const float2*)Wq, (const float2*)Wk,
            (const float2*)Wv, (const float2*)Wo,
            (__half2*)xhi,
            (__half2*)wqhi, (__half2*)wqlo,
            (__half2*)wkhi, (__half2*)wklo,
            (__half2*)wvhi, (__half2*)wvlo,
            (__half2*)wohi, (__half2*)wolo);
    }

    // fused Q/K/V projections + rope/rms epilogue
    gemm_qkv<<<dim3(24, M / 128), 256, G_SMEM>>>(
        xhi, wqhi, wqlo, wkhi, wklo, wvhi, wvlo,
        qh, kh, kl, vh, cosp, sinp);

    // attention (heavy-first, per-warp masked-tile skip)
    attn_mma<<<dim3(S_ / 128, H_, B_), 256, A_SMEM>>>(
        qh, kh, kl, vh, chi);

    // output projection
    gemm_one<<<dim3(E_ / 128, M / 128), 256, G_SMEM>>>(
        chi, wohi, wolo, out, E_, E_);
}

// round 16
// speedup vs baseline: 1.1273x; 1.0309x over previous
#include <cuda_runtime.h>
#include <cuda_bf16.h>
#include <cuda_fp16.h>
#include <math.h>
#include <stdint.h>

#define B_  2
#define S_  2048
#define E_  2048
#define H_  16
#define KV_ 4
#define D_  128
#define WIN_ 1024

// fp16 scratch
__device__ __half g_xhi[(size_t)B_ * S_ * E_];
__device__ __half g_wqhi[(size_t)H_ * D_ * E_];
__device__ __half g_wkhi[(size_t)KV_ * D_ * E_];
__device__ __half g_wklo[(size_t)KV_ * D_ * E_];
__device__ __half g_wvhi[(size_t)KV_ * D_ * E_];
__device__ __half g_wohi[(size_t)E_ * H_ * D_];
__device__ __half g_wolo[(size_t)E_ * H_ * D_];
__device__ __half g_chi[(size_t)B_ * S_ * H_ * D_];

// fp16 attention operands
__device__ __half g_qh[(size_t)B_ * S_ * H_ * D_];
__device__ __half g_kh[(size_t)B_ * S_ * KV_ * D_];
__device__ __half g_kl[(size_t)B_ * S_ * KV_ * D_];
__device__ __half g_vh[(size_t)B_ * S_ * KV_ * D_];

// Q pre-scale: D^-0.5 * log2(e)  (softmax done in base-2)
#define QSCALE 0.12752820723310574f

// ---------------------------------------------------------------------------
// Fused fp16 splitter, 4 float2 per thread.
// x, Wq, Wv: hi only; Wk, Wo: hi+lo.
// ---------------------------------------------------------------------------
#define N2_X  ((size_t)B_ * S_ * E_ / 2)
#define N2_WQ ((size_t)H_ * D_ * E_ / 2)
#define N2_WK ((size_t)KV_ * D_ * E_ / 2)
#define N2_ALL (N2_X + 2 * N2_WQ + 2 * N2_WK)

__global__ __launch_bounds__(256) void split_all(
    const float2* __restrict__ x,  const float2* __restrict__ wq,
    const float2* __restrict__ wk, const float2* __restrict__ wv,
    const float2* __restrict__ wo,
    __half2* __restrict__ xhi,
    __half2* __restrict__ qhi,
    __half2* __restrict__ khi,  __half2* __restrict__ klo,
    __half2* __restrict__ vhi,
    __half2* __restrict__ ohi,  __half2* __restrict__ olo)
{
    size_t g = ((size_t)blockIdx.x * blockDim.x + threadIdx.x) * 4;
    if (g >= N2_ALL) return;

    const float2* src;
    __half2 *dh, *dl;
    size_t off = g;
    if (off < N2_X)                    { src = x;  dh = xhi; dl = nullptr; }
    else if ((off -= N2_X) < N2_WQ)    { src = wq; dh = qhi; dl = nullptr; }
    else if ((off -= N2_WQ) < N2_WK)   { src = wk; dh = khi; dl = klo; }
    else if ((off -= N2_WK) < N2_WK)   { src = wv; dh = vhi; dl = nullptr; }
    else { off -= N2_WK;                 src = wo; dh = ohi; dl = olo; }

    float2 vv[4] = {src[off], src[off + 1], src[off + 2], src[off + 3]};
    #pragma unroll
    for (int u = 0; u < 4; u++) {
        __half h0 = __float2half(vv[u].x);
        __half h1 = __float2half(vv[u].y);
        __half2 hh; hh.x = h0; hh.y = h1;
        dh[off + u] = hh;
        if (dl) {
            __half2 ll;
            ll.x = __float2half(vv[u].x - __half2float(h0));
            ll.y = __float2half(vv[u].y - __half2float(h1));
            dl[off + u] = ll;
        }
    }
}

// ---------------------------------------------------------------------------
// PTX helpers
// ---------------------------------------------------------------------------
#define CP16(dst, src) \
    asm volatile("cp.async.cg.shared.global [%0], [%1], 16;\n" :: "r"(dst), "l"(src))
#define CP_COMMIT() asm volatile("cp.async.commit_group;\n" ::)
#define CP_WAIT2()  asm volatile("cp.async.wait_group 2;\n" ::)
#define CP_WAIT1()  asm volatile("cp.async.wait_group 1;\n" ::)
#define CP_WAIT0()  asm volatile("cp.async.wait_group 0;\n" ::)

#define LDSM4(R, addr) \
    asm volatile("ldmatrix.sync.aligned.m8n8.x4.shared.b16 {%0,%1,%2,%3}, [%4];\n" \
        : "=r"(R[0]), "=r"(R[1]), "=r"(R[2]), "=r"(R[3]) : "r"(addr))
#define LDSM4T(R, addr) \
    asm volatile("ldmatrix.sync.aligned.m8n8.x4.trans.shared.b16 {%0,%1,%2,%3}, [%4];\n" \
        : "=r"(R[0]), "=r"(R[1]), "=r"(R[2]), "=r"(R[3]) : "r"(addr))

#define MMAF16(acc, a, b0, b1) \
    asm volatile("mma.sync.aligned.m16n8k16.row.col.f32.f16.f16.f32 " \
        "{%0,%1,%2,%3}, {%4,%5,%6,%7}, {%8,%9}, {%0,%1,%2,%3};\n" \
        : "+f"(acc[0]), "+f"(acc[1]), "+f"(acc[2]), "+f"(acc[3]) \
        : "r"(a[0]), "r"(a[1]), "r"(a[2]), "r"(a[3]), "r"(b0), "r"(b1))

__device__ __forceinline__ float ex2f(float x) {
    float r;
    asm("ex2.approx.f32 %0, %1;" : "=f"(r) : "f"(x));
    return r;
}

// ---------------------------------------------------------------------------
// GEMM core: C = Ah@Bh^T (+ Ah@Bl^T if Bl != nullptr)   (fp32 accum)
// 4-stage cp.async pipeline, 1 barrier/K16, 2 CTAs/SM.
// mode 0: fp32 out. mode 1: fp16 hi out. mode 2: rope+rms*oscale -> fp16.
// gemm_core is force-inlined; Bl==nullptr call sites get 1-pass code.
// ---------------------------------------------------------------------------
#define SSTR   24
#define TILE_B (128u * SSTR * 2u)       // 6144 B
#define STG_B  (3u * TILE_B)            // Ah|Bh|Bl = 18432 B
#define G_SMEM (4u * STG_B)             // 73728 B

__device__ __forceinline__ void gemm_core(
    const __half* __restrict__ Ah,
    const __half* __restrict__ Bh, const __half* __restrict__ Bl,
    float* __restrict__ C,
    __half* __restrict__ Chh, __half* __restrict__ Chl,
    int N, int K, int bm, int bn, char* smem, int mode,
    const float* __restrict__ cs, const float* __restrict__ sn, float oscale)
{
    const uint32_t sb = (uint32_t)__cvta_generic_to_shared(smem);
    const int tid = threadIdx.x;
    const int lane = tid & 31;
    const int wid = tid >> 5;
    const int wm = wid & 1;
    const int wn = wid >> 1;

    const int lrow = tid >> 1;
    const int lkc  = tid & 1;
    const __half* gah = Ah + (size_t)(bm * 128 + lrow) * K + lkc * 8;
    const __half* gbh = Bh + (size_t)(bn * 128 + lrow) * K + lkc * 8;
    const __half* gbl = Bl ? Bl + (size_t)(bn * 128 + lrow) * K + lkc * 8 : nullptr;
    const uint32_t sOff = (uint32_t)(lrow * SSTR + lkc * 8) * 2;

    const uint32_t aLn = (uint32_t)((wm * 64 + (lane & 15)) * SSTR + (lane >> 4) * 8) * 2;
    const uint32_t bLn = (uint32_t)((wn * 32 + ((lane >> 4) << 3) + (lane & 7)) * SSTR
                                    + ((lane >> 3) & 1) * 8) * 2;

    float acc[4][4][4];
    #pragma unroll
    for (int i = 0; i < 4; i++)
        #pragma unroll
        for (int j = 0; j < 4; j++)
            #pragma unroll
            for (int r = 0; r < 4; r++) acc[i][j][r] = 0.f;

    const int T = K / 16;

    auto stage_load = [&](uint32_t st, int kt) {
        uint32_t base = sb + st * STG_B + sOff;
        CP16(base,              gah + kt * 16);
        CP16(base + TILE_B,     gbh + kt * 16);
        if (Bl) CP16(base + 2 * TILE_B, gbl + kt * 16);
        CP_COMMIT();
    };

    stage_load(0, 0);
    stage_load(1, 1);
    stage_load(2, 2);

    for (int t = 0; t < T; t++) {
        CP_WAIT2();
        __syncthreads();

        const uint32_t ab = sb + (uint32_t)(t & 3) * STG_B;
        const uint32_t bb = ab + TILE_B;

        uint32_t ah[4][4], bh[2][4], bl[2][4];
        #pragma unroll
        for (int mt = 0; mt < 4; mt++)
            LDSM4(ah[mt], ab + aLn + mt * (16 * SSTR * 2));
        #pragma unroll
        for (int pr = 0; pr < 2; pr++) {
            LDSM4(bh[pr], bb + bLn + pr * (16 * SSTR * 2));
            if (Bl) LDSM4(bl[pr], bb + TILE_B + bLn + pr * (16 * SSTR * 2));
        }

        if (t + 3 < T) stage_load((uint32_t)((t + 3) & 3), t + 3);
        else           CP_COMMIT();

        #pragma unroll
        for (int mt = 0; mt < 4; mt++)
            #pragma unroll
            for (int nt = 0; nt < 4; nt++) {
                const int pr = nt >> 1, q = (nt & 1) * 2;
                MMAF16(acc[mt][nt], ah[mt], bh[pr][q], bh[pr][q + 1]);
            }
        if (Bl) {
            #pragma unroll
            for (int mt = 0; mt < 4; mt++)
                #pragma unroll
                for (int nt = 0; nt < 4; nt++) {
                    const int pr = nt >> 1, q = (nt & 1) * 2;
                    MMAF16(acc[mt][nt], ah[mt], bl[pr][q], bl[pr][q + 1]);
                }
        }
    }

    if (mode == 0) {
        #pragma unroll
        for (int mt = 0; mt < 4; mt++) {
            const int r0 = bm * 128 + wm * 64 + mt * 16 + (lane >> 2);
            #pragma unroll
            for (int nt = 0; nt < 4; nt++) {
                const int c0 = bn * 128 + wn * 32 + nt * 8 + (lane & 3) * 2;
                *(float2*)&C[(size_t)r0 * N + c0] =
                    make_float2(acc[mt][nt][0], acc[mt][nt][1]);
                *(float2*)&C[(size_t)(r0 + 8) * N + c0] =
                    make_float2(acc[mt][nt][2], acc[mt][nt][3]);
            }
        }
    } else if (mode == 1) {
        #pragma unroll
        for (int mt = 0; mt < 4; mt++) {
            const int r0 = bm * 128 + wm * 64 + mt * 16 + (lane >> 2);
            #pragma unroll
            for (int nt = 0; nt < 4; nt++) {
                const int c0 = bn * 128 + wn * 32 + nt * 8 + (lane & 3) * 2;
                #pragma unroll
                for (int hf = 0; hf < 2; hf++) {
                    __half2 hh = __floats2half2_rn(acc[mt][nt][hf * 2],
                                                   acc[mt][nt][hf * 2 + 1]);
                    *(uint32_t*)&Chh[(size_t)(r0 + hf * 8) * N + c0] =
                        *(uint32_t*)&hh;
                }
            }
        }
    } else {
        // mode 2: rope + rmsnorm (+oscale) fused epilogue -> fp16 hi (+lo)
        CP_WAIT0();
        __syncthreads();
        float* st = (float*)smem;
        #pragma unroll
        for (int mt = 0; mt < 4; mt++) {
            const int r0 = wm * 64 + mt * 16 + (lane >> 2);
            #pragma unroll
            for (int nt = 0; nt < 4; nt++) {
                const int c0 = wn * 32 + nt * 8 + (lane & 3) * 2;
                *(float2*)&st[r0 * 132 + c0] =
                    make_float2(acc[mt][nt][0], acc[mt][nt][1]);
                *(float2*)&st[(r0 + 8) * 132 + c0] =
                    make_float2(acc[mt][nt][2], acc[mt][nt][3]);
            }
        }
        __syncthreads();

        const int cb = bn * 128;
        for (int rr = 0; rr < 16; rr++) {
            int r = wid * 16 + rr;
            int grow_ = bm * 128 + r;
            int s = grow_ & (S_ - 1);
            float x1a = st[r * 132 + lane];
            float x1b = st[r * 132 + lane + 32];
            float x2a = st[r * 132 + lane + 64], x2b = st[r * 132 + lane + 96];
            float ca = cs[s * 64 + lane], cbv = cs[s * 64 + lane + 32];
            float sa = sn[s * 64 + lane], sbv = sn[s * 64 + lane + 32];

            float o1a =  x1a * ca  + x2a * sa;
            float o1b =  x1b * cbv + x2b * sbv;
            float o2a = -x1a * sa  + x2a * ca;
            float o2b = -x1b * sbv + x2b * cbv;

            float ss = o1a * o1a + o1b * o1b + o2a * o2a + o2b * o2b;
            #pragma unroll
            for (int o = 16; o; o >>= 1) ss += __shfl_xor_sync(0xffffffffu, ss, o);
            float scale = rsqrtf(ss * (1.f / 128.f) + 1.1920928955078125e-07f)
                        * oscale;

            float v4[4] = {o1a * scale, o1b * scale, o2a * scale, o2b * scale};
            size_t gb = (size_t)grow_ * N + cb + lane;
            #pragma unroll
            for (int u = 0; u < 4; u++) {
                __half hh = __float2half(v4[u]);
                Chh[gb + u * 32] = hh;
                if (Chl) Chl[gb + u * 32] =
                    __float2half(v4[u] - __half2float(hh));
            }
        }
    }
}

// Fused Q/K/V projection:
//   Q: 1-pass (output is fp16-hi anyway), rope/rms epilogue
//   K: 2-pass, rope/rms epilogue, hi+lo out
//   V: 1-pass, fp16 hi out
__global__ __launch_bounds__(256, 2) void gemm_qkv(
    const __half* __restrict__ xh,
    const __half* __restrict__ wqh,
    const __half* __restrict__ wkh, const __half* __restrict__ wkl,
    const __half* __restrict__ wvh,
    __half* __restrict__ qh, __half* __restrict__ kh, __half* __restrict__ kl,
    __half* __restrict__ vh,
    const float* __restrict__ cosp, const float* __restrict__ sinp)
{
    extern __shared__ char smem[];
    const int bx = blockIdx.x;
    if (bx < 16) {
        gemm_core(xh, wqh, nullptr, nullptr, qh, nullptr,
                  H_ * D_, E_, blockIdx.y, bx, smem, 2, cosp, sinp, QSCALE);
    } else if (bx < 20) {
        gemm_core(xh, wkh, wkl, nullptr, kh, kl,
                  KV_ * D_, E_, blockIdx.y, bx - 16, smem, 2, cosp, sinp, 1.f);
    } else {
        gemm_core(xh, wvh, nullptr, nullptr, vh, nullptr,
                  KV_ * D_, E_, blockIdx.y, bx - 20, smem, 1, nullptr, nullptr, 1.f);
    }
}

__global__ __launch_bounds__(256, 2) void gemm_one(
    const __half* __restrict__ Ah,
    const __half* __restrict__ Bh, const __half* __restrict__ Bl,
    float* __restrict__ C, int N, int K)
{
    extern __shared__ char smem[];
    gemm_core(Ah, Bh, Bl, C, nullptr, nullptr, N, K,
              blockIdx.y, blockIdx.x, smem, 0, nullptr, nullptr, 1.f);
}

// ---------------------------------------------------------------------------
// fp16 2-pass sliding-window flash attention; softmax in base-2.
// 1 CTA/SM, uncapped registers. Heavy-first q-tile order + per-warp
// fully-masked-tile skip (tile must intersect [ibase-1023, ibase+15]).
// ---------------------------------------------------------------------------
#define RB 17408   // 64 rows * 272 B (stride 136 fp16)
#define A_SMEM (6u * RB)

__global__ __launch_bounds__(256) void attn_mma(
    const __half* __restrict__ q_, const __half* __restrict__ kh_,
    const __half* __restrict__ kl_, const __half* __restrict__ vh_,
    __half* __restrict__ chi)
{
    extern __shared__ char smem[];
    const uint32_t sbase = (uint32_t)__cvta_generic_to_shared(smem);

    const int tid = threadIdx.x, lane = tid & 31, w = tid >> 5;
    const int q0 = (gridDim.x - 1 - blockIdx.x) * 128;
    const int h  = blockIdx.y, b = blockIdx.z;
    const int kvh = h >> 2;

    {
        int r = tid >> 1;
        size_t gbase = ((size_t)(b * S_ + q0 + r)) * (H_ * D_) + h * D_;
        const uint4* gq = (const uint4*)(q_ + gbase);
        #pragma unroll
        for (int u = 0; u < 8; u++) {
            int c = (tid & 1) * 8 + u;
            *(uint4*)(smem + (size_t)r * 272 + c * 16) = gq[c];
        }
    }
    __syncthreads();

    uint32_t ah[8][4];
    {
        uint32_t qro = (uint32_t)((w * 16 + (lane & 15)) * 272);
        #pragma unroll
        for (int d = 0; d < 8; d++) {
            uint32_t co = (uint32_t)((d * 16 + (lane >> 4) * 8) * 2);
            LDSM4(ah[d], sbase + qro + co);
        }
    }
    __syncthreads();

    float pacc[16][4];
    #pragma unroll
    for (int g = 0; g < 16; g++)
        #pragma unroll
        for (int r = 0; r < 4; r++) pacc[g][r] = 0.f;

    float m_run0 = -1e30f, m_run1 = -1e30f, l0 = 0.f, l1 = 0.f;

    const int ibase = q0 + w * 16;
    const int i0 = ibase + (lane >> 2);
    const int i1 = i0 + 8;

    int t0 = q0 - 1024; if (t0 < 0) t0 = 0;
    const int n = (q0 + 128 - t0) >> 6;

    const int crow = tid >> 2;
    const size_t grow = ((size_t)b * S_) * (KV_ * D_) + (size_t)kvh * D_;

    {
        size_t gb = grow + (size_t)(t0 + crow) * (KV_ * D_);
        #pragma unroll
        for (int u = 0; u < 4; u++) {
            int c = (tid & 3) * 4 + u;
            uint32_t so = (uint32_t)(crow * 272 + c * 16);
            CP16(sbase + so,          kh_ + gb + c * 8);
            CP16(sbase + RB + so,     kl_ + gb + c * 8);
            CP16(sbase + 2 * RB + so, vh_ + gb + c * 8);
        }
        CP_COMMIT();
    }

    for (int it = 0; it < n; it++) {
        const int t = t0 + it * 64;
        if (it + 1 < n) {
            uint32_t st = (uint32_t)((it + 1) & 1) * 3 * RB;
            size_t gb = grow + (size_t)(t + 64 + crow) * (KV_ * D_);
            #pragma unroll
            for (int u = 0; u < 4; u++) {
                int c = (tid & 3) * 4 + u;
                uint32_t so = st + (uint32_t)(crow * 272 + c * 16);
                CP16(sbase + so,          kh_ + gb + c * 8);
                CP16(sbase + RB + so,     kl_ + gb + c * 8);
                CP16(sbase + 2 * RB + so, vh_ + gb + c * 8);
            }
            CP_COMMIT();
            CP_WAIT1();
        } else {
            CP_WAIT0();
        }
        __syncthreads();

        const bool active = (t <= ibase + 15) && (t + 63 >= ibase - 1023);
        if (active) {

        const uint32_t khb = sbase + (uint32_t)(it & 1) * 3 * RB;
        const uint32_t klb = khb + RB;
        const uint32_t vhb = khb + 2 * RB;

        float sacc[8][4];
        #pragma unroll
        for (int g = 0; g < 8; g++)
            #pragma unroll
            for (int r = 0; r < 4; r++) sacc[g][r] = 0.f;

        #pragma unroll
        for (int d = 0; d < 8; d++) {
            uint32_t co = (uint32_t)((d * 16 + ((lane >> 3) & 1) * 8) * 2);
            #pragma unroll
            for (int g = 0; g < 4; g++) {
                uint32_t ro = (uint32_t)((g * 16 + ((lane >> 4) << 3) + (lane & 7)) * 272);
                uint32_t k4h[4], k4l[4];
                LDSM4(k4h, khb + ro + co);
                LDSM4(k4l, klb + ro + co);
                MMAF16(sacc[2 * g],     ah[d], k4h[0], k4h[1]);
                MMAF16(sacc[2 * g],     ah[d], k4l[0], k4l[1]);
                MMAF16(sacc[2 * g + 1], ah[d], k4h[2], k4h[3]);
                MMAF16(sacc[2 * g + 1], ah[d], k4l[2], k4l[3]);
            }
        }

        const bool need_mask = (t + 63 >= ibase) || (t + 1009 <= ibase);
        float m0 = -INFINITY, m1 = -INFINITY;
        #pragma unroll
        for (int g = 0; g < 8; g++) {
            float s0 = sacc[g][0], s1 = sacc[g][1];
            float s2 = sacc[g][2], s3 = sacc[g][3];
            if (need_mask) {
                int jb = t + g * 8 + 2 * (lane & 3);
                s0 = ((jb     <= i0) && (i0 - jb < 1024))     ? s0 : -INFINITY;
                s1 = ((jb + 1 <= i0) && (i0 - jb - 1 < 1024)) ? s1 : -INFINITY;
                s2 = ((jb     <= i1) && (i1 - jb < 1024))     ? s2 : -INFINITY;
                s3 = ((jb + 1 <= i1) && (i1 - jb - 1 < 1024)) ? s3 : -INFINITY;
                sacc[g][0] = s0; sacc[g][1] = s1;
                sacc[g][2] = s2; sacc[g][3] = s3;
            }
            m0 = fmaxf(m0, fmaxf(s0, s1));
            m1 = fmaxf(m1, fmaxf(s2, s3));
        }
        m0 = fmaxf(m0, __shfl_xor_sync(0xffffffffu, m0, 1));
        m0 = fmaxf(m0, __shfl_xor_sync(0xffffffffu, m0, 2));
        m1 = fmaxf(m1, __shfl_xor_sync(0xffffffffu, m1, 1));
        m1 = fmaxf(m1, __shfl_xor_sync(0xffffffffu, m1, 2));

        float mn0 = fmaxf(m_run0, m0), mn1 = fmaxf(m_run1, m1);
        float a0 = ex2f(m_run0 - mn0), a1 = ex2f(m_run1 - mn1);
        m_run0 = mn0; m_run1 = mn1;

        float rs0 = 0.f, rs1 = 0.f;
        #pragma unroll
        for (int g = 0; g < 8; g++) {
            float p0 = ex2f(sacc[g][0] - mn0);
            float p1 = ex2f(sacc[g][1] - mn0);
            float p2 = ex2f(sacc[g][2] - mn1);
            float p3 = ex2f(sacc[g][3] - mn1);
            sacc[g][0] = p0; sacc[g][1] = p1; sacc[g][2] = p2; sacc[g][3] = p3;
            rs0 += p0 + p1; rs1 += p2 + p3;
        }
        rs0 += __shfl_xor_sync(0xffffffffu, rs0, 1);
        rs0 += __shfl_xor_sync(0xffffffffu, rs0, 2);
        rs1 += __shfl_xor_sync(0xffffffffu, rs1, 1);
        rs1 += __shfl_xor_sync(0xffffffffu, rs1, 2);
        l0 = l0 * a0 + rs0;
        l1 = l1 * a1 + rs1;

        #pragma unroll
        for (int g = 0; g < 16; g++) {
            pacc[g][0] *= a0; pacc[g][1] *= a0;
            pacc[g][2] *= a1; pacc[g][3] *= a1;
        }

        // per-kt P conversion + PV
        #pragma unroll
        for (int kt = 0; kt < 4; kt++) {
            uint32_t ph[4], pl[4];
            #pragma unroll
            for (int qq = 0; qq < 2; qq++) {
                #pragma unroll
                for (int r2 = 0; r2 < 2; r2++) {
                    float x0 = sacc[2 * kt + qq][r2 * 2];
                    float x1 = sacc[2 * kt + qq][r2 * 2 + 1];
                    __half2 hh = __floats2half2_rn(x0, x1);
                    __half2 ll = __floats2half2_rn(
                        x0 - __half2float(hh.x), x1 - __half2float(hh.y));
                    ph[qq * 2 + r2] = *(uint32_t*)&hh;
                    pl[qq * 2 + r2] = *(uint32_t*)&ll;
                }
            }
            uint32_t ro = (uint32_t)((kt * 16 + (lane & 15)) * 272);
            uint32_t co = (uint32_t)(((lane >> 4) * 8) * 2);
            #pragma unroll
            for (int g = 0; g < 8; g++) {
                uint32_t v4h[4];
                LDSM4T(v4h, vhb + ro + co + g * 32);
                MMAF16(pacc[2 * g],     ph, v4h[0], v4h[1]);
                MMAF16(pacc[2 * g],     pl, v4h[0], v4h[1]);
                MMAF16(pacc[2 * g + 1], ph, v4h[2], v4h[3]);
                MMAF16(pacc[2 * g + 1], pl, v4h[2], v4h[3]);
            }
        }

        } // active
        __syncthreads();
    }

    float inv0 = 1.f / l0, inv1 = 1.f / l1;
    size_t base0 = ((size_t)(b * S_ + i0)) * (H_ * D_) + h * D_;
    size_t base1 = base0 + (size_t)8 * (H_ * D_);
    #pragma unroll
    for (int g = 0; g < 16; g++) {
        int col = g * 8 + 2 * (lane & 3);
        __half2 h0 = __floats2half2_rn(pacc[g][0] * inv0, pacc[g][1] * inv0);
        __half2 h1 = __floats2half2_rn(pacc[g][2] * inv1, pacc[g][3] * inv1);
        *(uint32_t*)&chi[base0 + col] = *(uint32_t*)&h0;
        *(uint32_t*)&chi[base1 + col] = *(uint32_t*)&h1;
    }
}

// ---------------------------------------------------------------------------
extern "C" void kernel_launch(void* const* d_in, const int* in_sizes, int n_in,
                              void* d_out, int out_size)
{
    const float* x    = (const float*)d_in[0];
    const float* cosp = (const float*)d_in[1];
    const float* sinp = (const float*)d_in[2];
    const float* Wq   = (const float*)d_in[3];
    const float* Wk   = (const float*)d_in[4];
    const float* Wv   = (const float*)d_in[5];
    const float* Wo   = (const float*)d_in[6];
    float* out = (float*)d_out;

    __half *xhi, *wqhi, *wkhi, *wklo, *wvhi, *wohi, *wolo;
    __half *chi, *qh, *kh, *kl, *vh;
    cudaGetSymbolAddress((void**)&xhi, g_xhi);
    cudaGetSymbolAddress((void**)&wqhi, g_wqhi);
    cudaGetSymbolAddress((void**)&wkhi, g_wkhi);
    cudaGetSymbolAddress((void**)&wklo, g_wklo);
    cudaGetSymbolAddress((void**)&wvhi, g_wvhi);
    cudaGetSymbolAddress((void**)&wohi, g_wohi);
    cudaGetSymbolAddress((void**)&wolo, g_wolo);
    cudaGetSymbolAddress((void**)&chi, g_chi);
    cudaGetSymbolAddress((void**)&qh, g_qh);
    cudaGetSymbolAddress((void**)&kh, g_kh);
    cudaGetSymbolAddress((void**)&kl, g_kl);
    cudaGetSymbolAddress((void**)&vh, g_vh);

    static bool attr_done = false;
    if (!attr_done) {
        cudaFuncSetAttribute(attn_mma,
            cudaFuncAttributeMaxDynamicSharedMemorySize, A_SMEM);
        cudaFuncSetAttribute(gemm_qkv,
            cudaFuncAttributeMaxDynamicSharedMemorySize, G_SMEM);
        cudaFuncSetAttribute(gemm_one,
            cudaFuncAttributeMaxDynamicSharedMemorySize, G_SMEM);
        attr_done = true;
    }

    const int M = B_ * S_;

    // fused split (x, Wq, Wv: hi only; Wk, Wo: hi+lo)
    {
        size_t blocks = (N2_ALL / 4 + 255) / 256;
        split_all<<<(unsigned)blocks, 256>>>(
            (const float2*)x, (const float2*)Wq, (const float2*)Wk,
            (const float2*)Wv, (const float2*)Wo,
            (__half2*)xhi,
            (__half2*)wqhi,
            (__half2*)wkhi, (__half2*)wklo,
            (__half2*)wvhi,
            (__half2*)wohi, (__half2*)wolo);
    }

    // fused Q/K/V projections (Q,V 1-pass; K 2-pass) + rope/rms epilogue
    gemm_qkv<<<dim3(24, M / 128), 256, G_SMEM>>>(
        xhi, wqhi, wkhi, wklo, wvhi,
        qh, kh, kl, vh, cosp, sinp);

    // attention (heavy-first, per-warp masked-tile skip)
    attn_mma<<<dim3(S_ / 128, H_, B_), 256, A_SMEM>>>(
        qh, kh, kl, vh, chi);

    // output projection (2-pass)
    gemm_one<<<dim3(E_ / 128, M / 128), 256, G_SMEM>>>(
        chi, wohi, wolo, out, E_, E_);
}

// round 17
// speedup vs baseline: 1.1903x; 1.0559x over previous
#include <cuda_runtime.h>
#include <cuda_bf16.h>
#include <cuda_fp16.h>
#include <math.h>
#include <stdint.h>

#define B_  2
#define S_  2048
#define E_  2048
#define H_  16
#define KV_ 4
#define D_  128
#define WIN_ 1024

// fp16 scratch
__device__ __half g_xhi[(size_t)B_ * S_ * E_];
__device__ __half g_wqhi[(size_t)H_ * D_ * E_];
__device__ __half g_wkhi[(size_t)KV_ * D_ * E_];
__device__ __half g_wklo[(size_t)KV_ * D_ * E_];
__device__ __half g_wvhi[(size_t)KV_ * D_ * E_];
__device__ __half g_wohi[(size_t)E_ * H_ * D_];
__device__ __half g_wolo[(size_t)E_ * H_ * D_];
__device__ __half g_chi[(size_t)B_ * S_ * H_ * D_];

// fp16 attention operands
__device__ __half g_qh[(size_t)B_ * S_ * H_ * D_];
__device__ __half g_kh[(size_t)B_ * S_ * KV_ * D_];
__device__ __half g_kl[(size_t)B_ * S_ * KV_ * D_];
__device__ __half g_vh[(size_t)B_ * S_ * KV_ * D_];

// Q pre-scale: D^-0.5 * log2(e)  (softmax done in base-2)
#define QSCALE 0.12752820723310574f

// ---------------------------------------------------------------------------
// Fused fp16 splitter, 4 float2 per thread.
// x, Wq, Wv: hi only; Wk, Wo: hi+lo.
// ---------------------------------------------------------------------------
#define N2_X  ((size_t)B_ * S_ * E_ / 2)
#define N2_WQ ((size_t)H_ * D_ * E_ / 2)
#define N2_WK ((size_t)KV_ * D_ * E_ / 2)
#define N2_ALL (N2_X + 2 * N2_WQ + 2 * N2_WK)

__global__ __launch_bounds__(256) void split_all(
    const float2* __restrict__ x,  const float2* __restrict__ wq,
    const float2* __restrict__ wk, const float2* __restrict__ wv,
    const float2* __restrict__ wo,
    __half2* __restrict__ xhi,
    __half2* __restrict__ qhi,
    __half2* __restrict__ khi,  __half2* __restrict__ klo,
    __half2* __restrict__ vhi,
    __half2* __restrict__ ohi,  __half2* __restrict__ olo)
{
    size_t g = ((size_t)blockIdx.x * blockDim.x + threadIdx.x) * 4;
    if (g >= N2_ALL) return;

    const float2* src;
    __half2 *dh, *dl;
    size_t off = g;
    if (off < N2_X)                    { src = x;  dh = xhi; dl = nullptr; }
    else if ((off -= N2_X) < N2_WQ)    { src = wq; dh = qhi; dl = nullptr; }
    else if ((off -= N2_WQ) < N2_WK)   { src = wk; dh = khi; dl = klo; }
    else if ((off -= N2_WK) < N2_WK)   { src = wv; dh = vhi; dl = nullptr; }
    else { off -= N2_WK;                 src = wo; dh = ohi; dl = olo; }

    float2 vv[4] = {src[off], src[off + 1], src[off + 2], src[off + 3]};
    #pragma unroll
    for (int u = 0; u < 4; u++) {
        __half h0 = __float2half(vv[u].x);
        __half h1 = __float2half(vv[u].y);
        __half2 hh; hh.x = h0; hh.y = h1;
        dh[off + u] = hh;
        if (dl) {
            __half2 ll;
            ll.x = __float2half(vv[u].x - __half2float(h0));
            ll.y = __float2half(vv[u].y - __half2float(h1));
            dl[off + u] = ll;
        }
    }
}

// ---------------------------------------------------------------------------
// PTX helpers
// ---------------------------------------------------------------------------
#define CP16(dst, src) \
    asm volatile("cp.async.cg.shared.global [%0], [%1], 16;\n" :: "r"(dst), "l"(src))
#define CP_COMMIT() asm volatile("cp.async.commit_group;\n" ::)
#define CP_WAIT2()  asm volatile("cp.async.wait_group 2;\n" ::)
#define CP_WAIT1()  asm volatile("cp.async.wait_group 1;\n" ::)
#define CP_WAIT0()  asm volatile("cp.async.wait_group 0;\n" ::)

#define LDSM4(R, addr) \
    asm volatile("ldmatrix.sync.aligned.m8n8.x4.shared.b16 {%0,%1,%2,%3}, [%4];\n" \
        : "=r"(R[0]), "=r"(R[1]), "=r"(R[2]), "=r"(R[3]) : "r"(addr))
#define LDSM4T(R, addr) \
    asm volatile("ldmatrix.sync.aligned.m8n8.x4.trans.shared.b16 {%0,%1,%2,%3}, [%4];\n" \
        : "=r"(R[0]), "=r"(R[1]), "=r"(R[2]), "=r"(R[3]) : "r"(addr))

#define MMAF16(acc, a, b0, b1) \
    asm volatile("mma.sync.aligned.m16n8k16.row.col.f32.f16.f16.f32 " \
        "{%0,%1,%2,%3}, {%4,%5,%6,%7}, {%8,%9}, {%0,%1,%2,%3};\n" \
        : "+f"(acc[0]), "+f"(acc[1]), "+f"(acc[2]), "+f"(acc[3]) \
        : "r"(a[0]), "r"(a[1]), "r"(a[2]), "r"(a[3]), "r"(b0), "r"(b1))

__device__ __forceinline__ float ex2f(float x) {
    float r;
    asm("ex2.approx.f32 %0, %1;" : "=f"(r) : "f"(x));
    return r;
}

// ---------------------------------------------------------------------------
// GEMM core: C = Ah@Bh^T (+ Ah@Bl^T if HAS_BL)   (fp32 accum)
// Compile-time HAS_BL -> no runtime branches in the mainloop.
// 4-stage cp.async pipeline, 1 barrier/K16, 2 CTAs/SM.
// mode 0: fp32 out. mode 1: fp16 hi out. mode 2: rope+rms*oscale -> fp16.
// ---------------------------------------------------------------------------
#define SSTR   24
#define TILE_B (128u * SSTR * 2u)       // 6144 B
#define STG_B  (3u * TILE_B)            // Ah|Bh|Bl = 18432 B
#define G_SMEM (4u * STG_B)             // 73728 B

template <bool HAS_BL>
__device__ __forceinline__ void gemm_core(
    const __half* __restrict__ Ah,
    const __half* __restrict__ Bh, const __half* __restrict__ Bl,
    float* __restrict__ C,
    __half* __restrict__ Chh, __half* __restrict__ Chl,
    int N, int K, int bm, int bn, char* smem, int mode,
    const float* __restrict__ cs, const float* __restrict__ sn, float oscale)
{
    const uint32_t sb = (uint32_t)__cvta_generic_to_shared(smem);
    const int tid = threadIdx.x;
    const int lane = tid & 31;
    const int wid = tid >> 5;
    const int wm = wid & 1;
    const int wn = wid >> 1;

    const int lrow = tid >> 1;
    const int lkc  = tid & 1;
    const __half* gah = Ah + (size_t)(bm * 128 + lrow) * K + lkc * 8;
    const __half* gbh = Bh + (size_t)(bn * 128 + lrow) * K + lkc * 8;
    const __half* gbl = HAS_BL ? Bl + (size_t)(bn * 128 + lrow) * K + lkc * 8
                               : nullptr;
    const uint32_t sOff = (uint32_t)(lrow * SSTR + lkc * 8) * 2;

    const uint32_t aLn = (uint32_t)((wm * 64 + (lane & 15)) * SSTR + (lane >> 4) * 8) * 2;
    const uint32_t bLn = (uint32_t)((wn * 32 + ((lane >> 4) << 3) + (lane & 7)) * SSTR
                                    + ((lane >> 3) & 1) * 8) * 2;

    float acc[4][4][4];
    #pragma unroll
    for (int i = 0; i < 4; i++)
        #pragma unroll
        for (int j = 0; j < 4; j++)
            #pragma unroll
            for (int r = 0; r < 4; r++) acc[i][j][r] = 0.f;

    const int T = K / 16;

    auto stage_load = [&](uint32_t st, int kt) {
        uint32_t base = sb + st * STG_B + sOff;
        CP16(base,              gah + kt * 16);
        CP16(base + TILE_B,     gbh + kt * 16);
        if (HAS_BL) CP16(base + 2 * TILE_B, gbl + kt * 16);
        CP_COMMIT();
    };

    stage_load(0, 0);
    stage_load(1, 1);
    stage_load(2, 2);

    for (int t = 0; t < T; t++) {
        CP_WAIT2();
        __syncthreads();

        const uint32_t ab = sb + (uint32_t)(t & 3) * STG_B;
        const uint32_t bb = ab + TILE_B;

        uint32_t ah[4][4], bh[2][4], bl[2][4];
        #pragma unroll
        for (int mt = 0; mt < 4; mt++)
            LDSM4(ah[mt], ab + aLn + mt * (16 * SSTR * 2));
        #pragma unroll
        for (int pr = 0; pr < 2; pr++) {
            LDSM4(bh[pr], bb + bLn + pr * (16 * SSTR * 2));
            if (HAS_BL) LDSM4(bl[pr], bb + TILE_B + bLn + pr * (16 * SSTR * 2));
        }

        if (t + 3 < T) stage_load((uint32_t)((t + 3) & 3), t + 3);
        else           CP_COMMIT();

        #pragma unroll
        for (int mt = 0; mt < 4; mt++)
            #pragma unroll
            for (int nt = 0; nt < 4; nt++) {
                const int pr = nt >> 1, q = (nt & 1) * 2;
                MMAF16(acc[mt][nt], ah[mt], bh[pr][q], bh[pr][q + 1]);
            }
        if (HAS_BL) {
            #pragma unroll
            for (int mt = 0; mt < 4; mt++)
                #pragma unroll
                for (int nt = 0; nt < 4; nt++) {
                    const int pr = nt >> 1, q = (nt & 1) * 2;
                    MMAF16(acc[mt][nt], ah[mt], bl[pr][q], bl[pr][q + 1]);
                }
        }
    }

    if (mode == 0) {
        #pragma unroll
        for (int mt = 0; mt < 4; mt++) {
            const int r0 = bm * 128 + wm * 64 + mt * 16 + (lane >> 2);
            #pragma unroll
            for (int nt = 0; nt < 4; nt++) {
                const int c0 = bn * 128 + wn * 32 + nt * 8 + (lane & 3) * 2;
                *(float2*)&C[(size_t)r0 * N + c0] =
                    make_float2(acc[mt][nt][0], acc[mt][nt][1]);
                *(float2*)&C[(size_t)(r0 + 8) * N + c0] =
                    make_float2(acc[mt][nt][2], acc[mt][nt][3]);
            }
        }
    } else if (mode == 1) {
        #pragma unroll
        for (int mt = 0; mt < 4; mt++) {
            const int r0 = bm * 128 + wm * 64 + mt * 16 + (lane >> 2);
            #pragma unroll
            for (int nt = 0; nt < 4; nt++) {
                const int c0 = bn * 128 + wn * 32 + nt * 8 + (lane & 3) * 2;
                #pragma unroll
                for (int hf = 0; hf < 2; hf++) {
                    __half2 hh = __floats2half2_rn(acc[mt][nt][hf * 2],
                                                   acc[mt][nt][hf * 2 + 1]);
                    *(uint32_t*)&Chh[(size_t)(r0 + hf * 8) * N + c0] =
                        *(uint32_t*)&hh;
                }
            }
        }
    } else {
        // mode 2: rope + rmsnorm (+oscale) fused epilogue -> fp16 hi (+lo)
        CP_WAIT0();
        __syncthreads();
        float* st = (float*)smem;
        #pragma unroll
        for (int mt = 0; mt < 4; mt++) {
            const int r0 = wm * 64 + mt * 16 + (lane >> 2);
            #pragma unroll
            for (int nt = 0; nt < 4; nt++) {
                const int c0 = wn * 32 + nt * 8 + (lane & 3) * 2;
                *(float2*)&st[r0 * 132 + c0] =
                    make_float2(acc[mt][nt][0], acc[mt][nt][1]);
                *(float2*)&st[(r0 + 8) * 132 + c0] =
                    make_float2(acc[mt][nt][2], acc[mt][nt][3]);
            }
        }
        __syncthreads();

        const int cb = bn * 128;
        for (int rr = 0; rr < 16; rr++) {
            int r = wid * 16 + rr;
            int grow_ = bm * 128 + r;
            int s = grow_ & (S_ - 1);
            float x1a = st[r * 132 + lane];
            float x1b = st[r * 132 + lane + 32];
            float x2a = st[r * 132 + lane + 64], x2b = st[r * 132 + lane + 96];
            float ca = cs[s * 64 + lane], cbv = cs[s * 64 + lane + 32];
            float sa = sn[s * 64 + lane], sbv = sn[s * 64 + lane + 32];

            float o1a =  x1a * ca  + x2a * sa;
            float o1b =  x1b * cbv + x2b * sbv;
            float o2a = -x1a * sa  + x2a * ca;
            float o2b = -x1b * sbv + x2b * cbv;

            float ss = o1a * o1a + o1b * o1b + o2a * o2a + o2b * o2b;
            #pragma unroll
            for (int o = 16; o; o >>= 1) ss += __shfl_xor_sync(0xffffffffu, ss, o);
            float scale = rsqrtf(ss * (1.f / 128.f) + 1.1920928955078125e-07f)
                        * oscale;

            float v4[4] = {o1a * scale, o1b * scale, o2a * scale, o2b * scale};
            size_t gb = (size_t)grow_ * N + cb + lane;
            #pragma unroll
            for (int u = 0; u < 4; u++) {
                __half hh = __float2half(v4[u]);
                Chh[gb + u * 32] = hh;
                if (Chl) Chl[gb + u * 32] =
                    __float2half(v4[u] - __half2float(hh));
            }
        }
    }
}

// Fused Q/K/V projection:
//   Q: 1-pass (output is fp16-hi anyway), rope/rms epilogue
//   K: 2-pass, rope/rms epilogue, hi+lo out
//   V: 1-pass, fp16 hi out
__global__ __launch_bounds__(256, 2) void gemm_qkv(
    const __half* __restrict__ xh,
    const __half* __restrict__ wqh,
    const __half* __restrict__ wkh, const __half* __restrict__ wkl,
    const __half* __restrict__ wvh,
    __half* __restrict__ qh, __half* __restrict__ kh, __half* __restrict__ kl,
    __half* __restrict__ vh,
    const float* __restrict__ cosp, const float* __restrict__ sinp)
{
    extern __shared__ char smem[];
    const int bx = blockIdx.x;
    if (bx < 16) {
        gemm_core<false>(xh, wqh, nullptr, nullptr, qh, nullptr,
                  H_ * D_, E_, blockIdx.y, bx, smem, 2, cosp, sinp, QSCALE);
    } else if (bx < 20) {
        gemm_core<true>(xh, wkh, wkl, nullptr, kh, kl,
                  KV_ * D_, E_, blockIdx.y, bx - 16, smem, 2, cosp, sinp, 1.f);
    } else {
        gemm_core<false>(xh, wvh, nullptr, nullptr, vh, nullptr,
                  KV_ * D_, E_, blockIdx.y, bx - 20, smem, 1, nullptr, nullptr, 1.f);
    }
}

__global__ __launch_bounds__(256, 2) void gemm_one(
    const __half* __restrict__ Ah,
    const __half* __restrict__ Bh, const __half* __restrict__ Bl,
    float* __restrict__ C, int N, int K)
{
    extern __shared__ char smem[];
    gemm_core<true>(Ah, Bh, Bl, C, nullptr, nullptr, N, K,
              blockIdx.y, blockIdx.x, smem, 0, nullptr, nullptr, 1.f);
}

// ---------------------------------------------------------------------------
// fp16 2-pass sliding-window flash attention; softmax in base-2.
// 1 CTA/SM, uncapped registers. Heavy-first q-tile order + per-warp
// fully-masked-tile skip (tile must intersect [ibase-1023, ibase+15]).
// ---------------------------------------------------------------------------
#define RB 17408   // 64 rows * 272 B (stride 136 fp16)
#define A_SMEM (6u * RB)

__global__ __launch_bounds__(256) void attn_mma(
    const __half* __restrict__ q_, const __half* __restrict__ kh_,
    const __half* __restrict__ kl_, const __half* __restrict__ vh_,
    __half* __restrict__ chi)
{
    extern __shared__ char smem[];
    const uint32_t sbase = (uint32_t)__cvta_generic_to_shared(smem);

    const int tid = threadIdx.x, lane = tid & 31, w = tid >> 5;
    const int q0 = (gridDim.x - 1 - blockIdx.x) * 128;
    const int h  = blockIdx.y, b = blockIdx.z;
    const int kvh = h >> 2;

    {
        int r = tid >> 1;
        size_t gbase = ((size_t)(b * S_ + q0 + r)) * (H_ * D_) + h * D_;
        const uint4* gq = (const uint4*)(q_ + gbase);
        #pragma unroll
        for (int u = 0; u < 8; u++) {
            int c = (tid & 1) * 8 + u;
            *(uint4*)(smem + (size_t)r * 272 + c * 16) = gq[c];
        }
    }
    __syncthreads();

    uint32_t ah[8][4];
    {
        uint32_t qro = (uint32_t)((w * 16 + (lane & 15)) * 272);
        #pragma unroll
        for (int d = 0; d < 8; d++) {
            uint32_t co = (uint32_t)((d * 16 + (lane >> 4) * 8) * 2);
            LDSM4(ah[d], sbase + qro + co);
        }
    }
    __syncthreads();

    float pacc[16][4];
    #pragma unroll
    for (int g = 0; g < 16; g++)
        #pragma unroll
        for (int r = 0; r < 4; r++) pacc[g][r] = 0.f;

    float m_run0 = -1e30f, m_run1 = -1e30f, l0 = 0.f, l1 = 0.f;

    const int ibase = q0 + w * 16;
    const int i0 = ibase + (lane >> 2);
    const int i1 = i0 + 8;

    int t0 = q0 - 1024; if (t0 < 0) t0 = 0;
    const int n = (q0 + 128 - t0) >> 6;

    const int crow = tid >> 2;
    const size_t grow = ((size_t)b * S_) * (KV_ * D_) + (size_t)kvh * D_;

    {
        size_t gb = grow + (size_t)(t0 + crow) * (KV_ * D_);
        #pragma unroll
        for (int u = 0; u < 4; u++) {
            int c = (tid & 3) * 4 + u;
            uint32_t so = (uint32_t)(crow * 272 + c * 16);
            CP16(sbase + so,          kh_ + gb + c * 8);
            CP16(sbase + RB + so,     kl_ + gb + c * 8);
            CP16(sbase + 2 * RB + so, vh_ + gb + c * 8);
        }
        CP_COMMIT();
    }

    for (int it = 0; it < n; it++) {
        const int t = t0 + it * 64;
        if (it + 1 < n) {
            uint32_t st = (uint32_t)((it + 1) & 1) * 3 * RB;
            size_t gb = grow + (size_t)(t + 64 + crow) * (KV_ * D_);
            #pragma unroll
            for (int u = 0; u < 4; u++) {
                int c = (tid & 3) * 4 + u;
                uint32_t so = st + (uint32_t)(crow * 272 + c * 16);
                CP16(sbase + so,          kh_ + gb + c * 8);
                CP16(sbase + RB + so,     kl_ + gb + c * 8);
                CP16(sbase + 2 * RB + so, vh_ + gb + c * 8);
            }
            CP_COMMIT();
            CP_WAIT1();
        } else {
            CP_WAIT0();
        }
        __syncthreads();

        const bool active = (t <= ibase + 15) && (t + 63 >= ibase - 1023);
        if (active) {

        const uint32_t khb = sbase + (uint32_t)(it & 1) * 3 * RB;
        const uint32_t klb = khb + RB;
        const uint32_t vhb = khb + 2 * RB;

        float sacc[8][4];
        #pragma unroll
        for (int g = 0; g < 8; g++)
            #pragma unroll
            for (int r = 0; r < 4; r++) sacc[g][r] = 0.f;

        #pragma unroll
        for (int d = 0; d < 8; d++) {
            uint32_t co = (uint32_t)((d * 16 + ((lane >> 3) & 1) * 8) * 2);
            #pragma unroll
            for (int g = 0; g < 4; g++) {
                uint32_t ro = (uint32_t)((g * 16 + ((lane >> 4) << 3) + (lane & 7)) * 272);
                uint32_t k4h[4], k4l[4];
                LDSM4(k4h, khb + ro + co);
                LDSM4(k4l, klb + ro + co);
                MMAF16(sacc[2 * g],     ah[d], k4h[0], k4h[1]);
                MMAF16(sacc[2 * g],     ah[d], k4l[0], k4l[1]);
                MMAF16(sacc[2 * g + 1], ah[d], k4h[2], k4h[3]);
                MMAF16(sacc[2 * g + 1], ah[d], k4l[2], k4l[3]);
            }
        }

        const bool need_mask = (t + 63 >= ibase) || (t + 1009 <= ibase);
        float m0 = -INFINITY, m1 = -INFINITY;
        #pragma unroll
        for (int g = 0; g < 8; g++) {
            float s0 = sacc[g][0], s1 = sacc[g][1];
            float s2 = sacc[g][2], s3 = sacc[g][3];
            if (need_mask) {
                int jb = t + g * 8 + 2 * (lane & 3);
                s0 = ((jb     <= i0) && (i0 - jb < 1024))     ? s0 : -INFINITY;
                s1 = ((jb + 1 <= i0) && (i0 - jb - 1 < 1024)) ? s1 : -INFINITY;
                s2 = ((jb     <= i1) && (i1 - jb < 1024))     ? s2 : -INFINITY;
                s3 = ((jb + 1 <= i1) && (i1 - jb - 1 < 1024)) ? s3 : -INFINITY;
                sacc[g][0] = s0; sacc[g][1] = s1;
                sacc[g][2] = s2; sacc[g][3] = s3;
            }
            m0 = fmaxf(m0, fmaxf(s0, s1));
            m1 = fmaxf(m1, fmaxf(s2, s3));
        }
        m0 = fmaxf(m0, __shfl_xor_sync(0xffffffffu, m0, 1));
        m0 = fmaxf(m0, __shfl_xor_sync(0xffffffffu, m0, 2));
        m1 = fmaxf(m1, __shfl_xor_sync(0xffffffffu, m1, 1));
        m1 = fmaxf(m1, __shfl_xor_sync(0xffffffffu, m1, 2));

        float mn0 = fmaxf(m_run0, m0), mn1 = fmaxf(m_run1, m1);
        float a0 = ex2f(m_run0 - mn0), a1 = ex2f(m_run1 - mn1);
        m_run0 = mn0; m_run1 = mn1;

        float rs0 = 0.f, rs1 = 0.f;
        #pragma unroll
        for (int g = 0; g < 8; g++) {
            float p0 = ex2f(sacc[g][0] - mn0);
            float p1 = ex2f(sacc[g][1] - mn0);
            float p2 = ex2f(sacc[g][2] - mn1);
            float p3 = ex2f(sacc[g][3] - mn1);
            sacc[g][0] = p0; sacc[g][1] = p1; sacc[g][2] = p2; sacc[g][3] = p3;
            rs0 += p0 + p1; rs1 += p2 + p3;
        }
        rs0 += __shfl_xor_sync(0xffffffffu, rs0, 1);
        rs0 += __shfl_xor_sync(0xffffffffu, rs0, 2);
        rs1 += __shfl_xor_sync(0xffffffffu, rs1, 1);
        rs1 += __shfl_xor_sync(0xffffffffu, rs1, 2);
        l0 = l0 * a0 + rs0;
        l1 = l1 * a1 + rs1;

        #pragma unroll
        for (int g = 0; g < 16; g++) {
            pacc[g][0] *= a0; pacc[g][1] *= a0;
            pacc[g][2] *= a1; pacc[g][3] *= a1;
        }

        // per-kt P conversion + PV
        #pragma unroll
        for (int kt = 0; kt < 4; kt++) {
            uint32_t ph[4], pl[4];
            #pragma unroll
            for (int qq = 0; qq < 2; qq++) {
                #pragma unroll
                for (int r2 = 0; r2 < 2; r2++) {
                    float x0 = sacc[2 * kt + qq][r2 * 2];
                    float x1 = sacc[2 * kt + qq][r2 * 2 + 1];
                    __half2 hh = __floats2half2_rn(x0, x1);
                    __half2 ll = __floats2half2_rn(
                        x0 - __half2float(hh.x), x1 - __half2float(hh.y));
                    ph[qq * 2 + r2] = *(uint32_t*)&hh;
                    pl[qq * 2 + r2] = *(uint32_t*)&ll;
                }
            }
            uint32_t ro = (uint32_t)((kt * 16 + (lane & 15)) * 272);
            uint32_t co = (uint32_t)(((lane >> 4) * 8) * 2);
            #pragma unroll
            for (int g = 0; g < 8; g++) {
                uint32_t v4h[4];
                LDSM4T(v4h, vhb + ro + co + g * 32);
                MMAF16(pacc[2 * g],     ph, v4h[0], v4h[1]);
                MMAF16(pacc[2 * g],     pl, v4h[0], v4h[1]);
                MMAF16(pacc[2 * g + 1], ph, v4h[2], v4h[3]);
                MMAF16(pacc[2 * g + 1], pl, v4h[2], v4h[3]);
            }
        }

        } // active
        __syncthreads();
    }

    float inv0 = 1.f / l0, inv1 = 1.f / l1;
    size_t base0 = ((size_t)(b * S_ + i0)) * (H_ * D_) + h * D_;
    size_t base1 = base0 + (size_t)8 * (H_ * D_);
    #pragma unroll
    for (int g = 0; g < 16; g++) {
        int col = g * 8 + 2 * (lane & 3);
        __half2 h0 = __floats2half2_rn(pacc[g][0] * inv0, pacc[g][1] * inv0);
        __half2 h1 = __floats2half2_rn(pacc[g][2] * inv1, pacc[g][3] * inv1);
        *(uint32_t*)&chi[base0 + col] = *(uint32_t*)&h0;
        *(uint32_t*)&chi[base1 + col] = *(uint32_t*)&h1;
    }
}

// ---------------------------------------------------------------------------
extern "C" void kernel_launch(void* const* d_in, const int* in_sizes, int n_in,
                              void* d_out, int out_size)
{
    const float* x    = (const float*)d_in[0];
    const float* cosp = (const float*)d_in[1];
    const float* sinp = (const float*)d_in[2];
    const float* Wq   = (const float*)d_in[3];
    const float* Wk   = (const float*)d_in[4];
    const float* Wv   = (const float*)d_in[5];
    const float* Wo   = (const float*)d_in[6];
    float* out = (float*)d_out;

    __half *xhi, *wqhi, *wkhi, *wklo, *wvhi, *wohi, *wolo;
    __half *chi, *qh, *kh, *kl, *vh;
    cudaGetSymbolAddress((void**)&xhi, g_xhi);
    cudaGetSymbolAddress((void**)&wqhi, g_wqhi);
    cudaGetSymbolAddress((void**)&wkhi, g_wkhi);
    cudaGetSymbolAddress((void**)&wklo, g_wklo);
    cudaGetSymbolAddress((void**)&wvhi, g_wvhi);
    cudaGetSymbolAddress((void**)&wohi, g_wohi);
    cudaGetSymbolAddress((void**)&wolo, g_wolo);
    cudaGetSymbolAddress((void**)&chi, g_chi);
    cudaGetSymbolAddress((void**)&qh, g_qh);
    cudaGetSymbolAddress((void**)&kh, g_kh);
    cudaGetSymbolAddress((void**)&kl, g_kl);
    cudaGetSymbolAddress((void**)&vh, g_vh);

    static bool attr_done = false;
    if (!attr_done) {
        cudaFuncSetAttribute(attn_mma,
            cudaFuncAttributeMaxDynamicSharedMemorySize, A_SMEM);
        cudaFuncSetAttribute(gemm_qkv,
            cudaFuncAttributeMaxDynamicSharedMemorySize, G_SMEM);
        cudaFuncSetAttribute(gemm_one,
            cudaFuncAttributeMaxDynamicSharedMemorySize, G_SMEM);
        attr_done = true;
    }

    const int M = B_ * S_;

    // fused split (x, Wq, Wv: hi only; Wk, Wo: hi+lo)
    {
        size_t blocks = (N2_ALL / 4 + 255) / 256;
        split_all<<<(unsigned)blocks, 256>>>(
            (const float2*)x, (const float2*)Wq, (const float2*)Wk,
            (const float2*)Wv, (const float2*)Wo,
            (__half2*)xhi,
            (__half2*)wqhi,
            (__half2*)wkhi, (__half2*)wklo,
            (__half2*)wvhi,
            (__half2*)wohi, (__half2*)wolo);
    }

    // fused Q/K/V projections (Q,V 1-pass; K 2-pass) + rope/rms epilogue
    gemm_qkv<<<dim3(24, M / 128), 256, G_SMEM>>>(
        xhi, wqhi, wkhi, wklo, wvhi,
        qh, kh, kl, vh, cosp, sinp);

    // attention (heavy-first, per-warp masked-tile skip)
    attn_mma<<<dim3(S_ / 128, H_, B_), 256, A_SMEM>>>(
        qh, kh, kl, vh, chi);

    // output projection (2-pass, compile-time)
    gemm_one<<<dim3(E_ / 128, M / 128), 256, G_SMEM>>>(
        chi, wohi, wolo, out, E_, E_);
}